// round 1
// baseline (speedup 1.0000x reference)
#include <cuda_runtime.h>

#define NUM_HEADS 8
#define D_MODEL   512
#define DK        64
#define SEQ       2048
#define BATCH     4
#define M_TOTAL   (BATCH * SEQ)   // 8192

// Scratch (device globals — no allocation allowed)
__device__ float g_Q[BATCH * NUM_HEADS * SEQ * DK];
__device__ float g_K[BATCH * NUM_HEADS * SEQ * DK];
__device__ float g_V[BATCH * NUM_HEADS * SEQ * DK];
__device__ float g_AO[M_TOTAL * D_MODEL];

// ---------------------------------------------------------------------------
// Fast exp2: 5-FMA polynomial + exponent bit-stuff. Avoids MUFU.EX2 which is
// quarter-rate (rt=8/SMSP) and would cost ~1ms for the 134M softmax exps.
// Valid for t <= 0 (softmax domain); clamped at -126 to keep the exponent
// bit-trick in normal range.
// ---------------------------------------------------------------------------
__device__ __forceinline__ float fexp2(float t) {
    t = fmaxf(t, -126.0f);
    float fi = floorf(t);
    float f  = t - fi;                 // f in [0,1)
    float p  = fmaf(f, 1.33335581e-3f, 9.61812910e-3f);
    p = fmaf(p, f, 5.55041087e-2f);
    p = fmaf(p, f, 2.40226507e-1f);
    p = fmaf(p, f, 6.93147181e-1f);
    p = fmaf(p, f, 1.0f);
    return __int_as_float(((int)fi + 127) << 23) * p;
}

// ---------------------------------------------------------------------------
// SGEMM: C[M x 512] = A[M x 512] @ W[512 x 512] + bias
// 128x128 block tile, BK=16, 256 threads, 8x8 per-thread fragment.
// HEADOUT=1: write to head-split layout (B, H, L, 64) for attention.
// HEADOUT=0: plain row-major (final output projection).
// ---------------------------------------------------------------------------
template <int HEADOUT>
__global__ __launch_bounds__(256) void gemm128(const float* __restrict__ A,
                                               const float* __restrict__ W,
                                               const float* __restrict__ bias,
                                               float* __restrict__ C) {
    __shared__ __align__(16) float As[16][132];  // transposed A tile [k][m], pad for banks
    __shared__ __align__(16) float Bs[16][128];  // natural B tile [k][n]

    const int tid = threadIdx.x;
    const int tx  = tid & 15;
    const int ty  = tid >> 4;
    const int m0  = blockIdx.y * 128;
    const int n0  = blockIdx.x * 128;

    const int ar  = tid >> 2;          // 0..63  (A tile row, plus +64 on 2nd iter)
    const int akq = (tid & 3) << 2;    // 0,4,8,12 (k offset, float4)
    const int bk  = tid >> 5;          // 0..7   (B tile k-row, plus +8)
    const int bc  = (tid & 31) << 2;   // 0..124 (n offset, float4)

    float acc[8][8];
#pragma unroll
    for (int i = 0; i < 8; i++)
#pragma unroll
        for (int j = 0; j < 8; j++) acc[i][j] = 0.0f;

    for (int k0 = 0; k0 < 512; k0 += 16) {
#pragma unroll
        for (int it = 0; it < 2; it++) {
            int r = ar + it * 64;
            float4 av = *(const float4*)&A[(size_t)(m0 + r) * 512 + k0 + akq];
            As[akq + 0][r] = av.x;
            As[akq + 1][r] = av.y;
            As[akq + 2][r] = av.z;
            As[akq + 3][r] = av.w;
            int kk = bk + it * 8;
            *(float4*)&Bs[kk][bc] =
                *(const float4*)&W[(size_t)(k0 + kk) * 512 + n0 + bc];
        }
        __syncthreads();

#pragma unroll
        for (int kk = 0; kk < 16; kk++) {
            float a[8], b[8];
            *(float4*)&a[0] = *(const float4*)&As[kk][ty * 8];
            *(float4*)&a[4] = *(const float4*)&As[kk][ty * 8 + 4];
            *(float4*)&b[0] = *(const float4*)&Bs[kk][tx * 8];
            *(float4*)&b[4] = *(const float4*)&Bs[kk][tx * 8 + 4];
#pragma unroll
            for (int i = 0; i < 8; i++)
#pragma unroll
                for (int j = 0; j < 8; j++)
                    acc[i][j] = fmaf(a[i], b[j], acc[i][j]);
        }
        __syncthreads();
    }

    // Epilogue: bias + store
#pragma unroll
    for (int i = 0; i < 8; i++) {
        int m = m0 + ty * 8 + i;
#pragma unroll
        for (int j4 = 0; j4 < 2; j4++) {
            int n = n0 + tx * 8 + j4 * 4;
            float4 v;
            v.x = acc[i][j4 * 4 + 0] + bias[n + 0];
            v.y = acc[i][j4 * 4 + 1] + bias[n + 1];
            v.z = acc[i][j4 * 4 + 2] + bias[n + 2];
            v.w = acc[i][j4 * 4 + 3] + bias[n + 3];
            if (HEADOUT) {
                int b = m >> 11, l = m & 2047;
                int h = n >> 6,  d = n & 63;
                *(float4*)&C[((size_t)((b << 3) + h) * SEQ + l) * DK + d] = v;
            } else {
                *(float4*)&C[(size_t)m * 512 + n] = v;
            }
        }
    }
}

// ---------------------------------------------------------------------------
// Flash-attention (full softmax semantics, key mask). One block = one (b,h)
// pair x 64 query rows. 256 threads as 16x16; 4x4 fragments.
// smem: QT[d][r], KT[d][c] transposed (float4 operand reads), V natural,
// P natural. Stride 68 for alignment + bank spread.
// ---------------------------------------------------------------------------
#define SMS 68
#define ATTN_SMEM_BYTES ((4 * 64 * SMS + 64) * 4)

__global__ __launch_bounds__(256) void attn_kernel(const float* __restrict__ Q,
                                                   const float* __restrict__ K,
                                                   const float* __restrict__ V,
                                                   const int* __restrict__ mask,
                                                   float* __restrict__ AO) {
    extern __shared__ __align__(16) float sm[];
    float* QT  = sm;                 // [64][SMS]  QT[d*SMS + r]
    float* KT  = QT + 64 * SMS;      // [64][SMS]  KT[d*SMS + c]
    float* Vs  = KT + 64 * SMS;      // [64][SMS]  Vs[c*SMS + d]
    float* Ps  = Vs + 64 * SMS;      // [64][SMS]  Ps[r*SMS + c]
    float* mkS = Ps + 64 * SMS;      // [64] mask flags

    const int tid = threadIdx.x;
    const int tx  = tid & 15;
    const int ty  = tid >> 4;
    const int bh  = blockIdx.y;
    const int b   = bh >> 3;
    const int h   = bh & 7;
    const int q0  = blockIdx.x * 64;

    const float* Qp = Q + (size_t)bh * SEQ * DK;
    const float* Kp = K + (size_t)bh * SEQ * DK;
    const float* Vp = V + (size_t)bh * SEQ * DK;

    // Load Q tile transposed: QT[d][r]
    {
        int idx = tid;
#pragma unroll
        for (int it = 0; it < 4; it++, idx += 256) {
            int r = idx >> 4;
            int d = (idx & 15) << 2;
            float4 v = *(const float4*)&Qp[(size_t)(q0 + r) * DK + d];
            QT[(d + 0) * SMS + r] = v.x;
            QT[(d + 1) * SMS + r] = v.y;
            QT[(d + 2) * SMS + r] = v.z;
            QT[(d + 3) * SMS + r] = v.w;
        }
    }

    const float L2E = 1.4426950408889634f;  // log2(e)
    float m_i[4], l_i[4], o[4][4];
#pragma unroll
    for (int i = 0; i < 4; i++) {
        m_i[i] = -1e30f;
        l_i[i] = 0.0f;
#pragma unroll
        for (int j = 0; j < 4; j++) o[i][j] = 0.0f;
    }

    for (int kt = 0; kt < SEQ; kt += 64) {
        __syncthreads();  // prior-iter smem reads done (also covers Q store on iter 0)

        // Load K transposed, V natural, mask
        {
            int idx = tid;
#pragma unroll
            for (int it = 0; it < 4; it++, idx += 256) {
                int c = idx >> 4;
                int d = (idx & 15) << 2;
                float4 kv = *(const float4*)&Kp[(size_t)(kt + c) * DK + d];
                KT[(d + 0) * SMS + c] = kv.x;
                KT[(d + 1) * SMS + c] = kv.y;
                KT[(d + 2) * SMS + c] = kv.z;
                KT[(d + 3) * SMS + c] = kv.w;
                *(float4*)&Vs[c * SMS + d] =
                    *(const float4*)&Vp[(size_t)(kt + c) * DK + d];
            }
            if (tid < 64) mkS[tid] = (mask[b * SEQ + kt + tid] == 0) ? 0.0f : 1.0f;
        }
        __syncthreads();

        // S = Q @ K^T  (4x4 fragment: rows 4ty+i, cols 4tx+j)
        float s[4][4];
#pragma unroll
        for (int i = 0; i < 4; i++)
#pragma unroll
            for (int j = 0; j < 4; j++) s[i][j] = 0.0f;

#pragma unroll 8
        for (int d = 0; d < 64; d++) {
            float4 qa = *(const float4*)&QT[d * SMS + 4 * ty];
            float4 kb = *(const float4*)&KT[d * SMS + 4 * tx];
            float a[4] = {qa.x, qa.y, qa.z, qa.w};
            float bb[4] = {kb.x, kb.y, kb.z, kb.w};
#pragma unroll
            for (int i = 0; i < 4; i++)
#pragma unroll
                for (int j = 0; j < 4; j++)
                    s[i][j] = fmaf(a[i], bb[j], s[i][j]);
        }

        float mk4[4];
#pragma unroll
        for (int j = 0; j < 4; j++) mk4[j] = mkS[4 * tx + j];

        // Online softmax per row
#pragma unroll
        for (int i = 0; i < 4; i++) {
            float sv[4];
#pragma unroll
            for (int j = 0; j < 4; j++)
                sv[j] = (mk4[j] != 0.0f) ? s[i][j] * 0.125f : -1e30f;

            float tm = fmaxf(fmaxf(sv[0], sv[1]), fmaxf(sv[2], sv[3]));
            tm = fmaxf(tm, __shfl_xor_sync(0xffffffffu, tm, 1));
            tm = fmaxf(tm, __shfl_xor_sync(0xffffffffu, tm, 2));
            tm = fmaxf(tm, __shfl_xor_sync(0xffffffffu, tm, 4));
            tm = fmaxf(tm, __shfl_xor_sync(0xffffffffu, tm, 8));

            float mn = fmaxf(m_i[i], tm);
            float al = fexp2((m_i[i] - mn) * L2E);
            m_i[i] = mn;

            float rs = 0.0f;
#pragma unroll
            for (int j = 0; j < 4; j++) {
                float p = fexp2((sv[j] - mn) * L2E) * mk4[j];
                Ps[(4 * ty + i) * SMS + 4 * tx + j] = p;
                rs += p;
            }
            rs += __shfl_xor_sync(0xffffffffu, rs, 1);
            rs += __shfl_xor_sync(0xffffffffu, rs, 2);
            rs += __shfl_xor_sync(0xffffffffu, rs, 4);
            rs += __shfl_xor_sync(0xffffffffu, rs, 8);

            l_i[i] = l_i[i] * al + rs;
#pragma unroll
            for (int j = 0; j < 4; j++) o[i][j] *= al;
        }

        // P row r is produced and consumed within one warp (same ty group)
        __syncwarp();

        // O += P @ V
#pragma unroll 8
        for (int c = 0; c < 64; c++) {
            float p0 = Ps[(4 * ty + 0) * SMS + c];
            float p1 = Ps[(4 * ty + 1) * SMS + c];
            float p2 = Ps[(4 * ty + 2) * SMS + c];
            float p3 = Ps[(4 * ty + 3) * SMS + c];
            float4 vv = *(const float4*)&Vs[c * SMS + 4 * tx];
            o[0][0] = fmaf(p0, vv.x, o[0][0]);
            o[0][1] = fmaf(p0, vv.y, o[0][1]);
            o[0][2] = fmaf(p0, vv.z, o[0][2]);
            o[0][3] = fmaf(p0, vv.w, o[0][3]);
            o[1][0] = fmaf(p1, vv.x, o[1][0]);
            o[1][1] = fmaf(p1, vv.y, o[1][1]);
            o[1][2] = fmaf(p1, vv.z, o[1][2]);
            o[1][3] = fmaf(p1, vv.w, o[1][3]);
            o[2][0] = fmaf(p2, vv.x, o[2][0]);
            o[2][1] = fmaf(p2, vv.y, o[2][1]);
            o[2][2] = fmaf(p2, vv.z, o[2][2]);
            o[2][3] = fmaf(p2, vv.w, o[2][3]);
            o[3][0] = fmaf(p3, vv.x, o[3][0]);
            o[3][1] = fmaf(p3, vv.y, o[3][1]);
            o[3][2] = fmaf(p3, vv.z, o[3][2]);
            o[3][3] = fmaf(p3, vv.w, o[3][3]);
        }
    }

    // Normalize and write to (B, L, H*64) layout for the output projection
#pragma unroll
    for (int i = 0; i < 4; i++) {
        float inv = 1.0f / l_i[i];
        int qrow = q0 + 4 * ty + i;
        float4 v;
        v.x = o[i][0] * inv;
        v.y = o[i][1] * inv;
        v.z = o[i][2] * inv;
        v.w = o[i][3] * inv;
        *(float4*)&AO[(size_t)(b * SEQ + qrow) * D_MODEL + h * 64 + 4 * tx] = v;
    }
}

// ---------------------------------------------------------------------------
// Launch: 3 projection GEMMs -> attention -> output GEMM. All plain launches,
// graph-capturable, zero allocations.
// ---------------------------------------------------------------------------
extern "C" void kernel_launch(void* const* d_in, const int* in_sizes, int n_in,
                              void* d_out, int out_size) {
    const float* query = (const float*)d_in[0];
    const float* key   = (const float*)d_in[1];
    const float* value = (const float*)d_in[2];
    const int*   mask  = (const int*)d_in[3];
    const float* Wq = (const float*)d_in[4];
    const float* bq = (const float*)d_in[5];
    const float* Wk = (const float*)d_in[6];
    const float* bk = (const float*)d_in[7];
    const float* Wv = (const float*)d_in[8];
    const float* bv = (const float*)d_in[9];
    const float* Wo = (const float*)d_in[10];
    const float* bo = (const float*)d_in[11];

    float *Qb, *Kb, *Vb, *AOb;
    cudaGetSymbolAddress((void**)&Qb, g_Q);
    cudaGetSymbolAddress((void**)&Kb, g_K);
    cudaGetSymbolAddress((void**)&Vb, g_V);
    cudaGetSymbolAddress((void**)&AOb, g_AO);

    cudaFuncSetAttribute(attn_kernel,
                         cudaFuncAttributeMaxDynamicSharedMemorySize,
                         ATTN_SMEM_BYTES);

    dim3 gg(D_MODEL / 128, M_TOTAL / 128);  // (4, 64)
    dim3 gb(256);

    gemm128<1><<<gg, gb>>>(query, Wq, bq, Qb);
    gemm128<1><<<gg, gb>>>(key,   Wk, bk, Kb);
    gemm128<1><<<gg, gb>>>(value, Wv, bv, Vb);

    attn_kernel<<<dim3(SEQ / 64, BATCH * NUM_HEADS), 256, ATTN_SMEM_BYTES>>>(
        Qb, Kb, Vb, mask, AOb);

    gemm128<0><<<gg, gb>>>(AOb, Wo, bo, (float*)d_out);
}

// round 7
// speedup vs baseline: 1.9447x; 1.9447x over previous
#include <cuda_runtime.h>
#include <cuda_bf16.h>
#include <cstdint>

#define NUM_HEADS 8
#define D_MODEL   512
#define DK        64
#define SEQ       2048
#define BATCH     4
#define MT        (BATCH * SEQ)        // 8192
#define BH        (BATCH * NUM_HEADS)  // 32

// ============================================================================
// Scratch (device globals — no allocation allowed)
// ============================================================================
__device__ __align__(16) __nv_bfloat16 g_Ah[MT * D_MODEL];
__device__ __align__(16) __nv_bfloat16 g_Al[MT * D_MODEL];
__device__ __align__(16) __nv_bfloat16 g_Wth[D_MODEL * D_MODEL];
__device__ __align__(16) __nv_bfloat16 g_Wtl[D_MODEL * D_MODEL];
__device__ __align__(16) __nv_bfloat16 g_Qh[BH * SEQ * DK];
__device__ __align__(16) __nv_bfloat16 g_Ql[BH * SEQ * DK];
__device__ __align__(16) __nv_bfloat16 g_Kh[BH * SEQ * DK];
__device__ __align__(16) __nv_bfloat16 g_Kl[BH * SEQ * DK];
__device__ __align__(16) float         g_Vf[BH * SEQ * DK];
__device__ __align__(16) __nv_bfloat16 g_Vth[BH * DK * SEQ];
__device__ __align__(16) __nv_bfloat16 g_Vtl[BH * DK * SEQ];
__device__ __align__(16) float         g_AO[MT * D_MODEL];

// ============================================================================
// Warp-MMA primitives (PTX ISA 7.x — legal at compute_103 baseline)
// ============================================================================
__device__ __forceinline__ uint32_t smem_to_u32(const void* p) {
    uint32_t a;
    asm("{ .reg .u64 t; cvta.to.shared.u64 t, %1; cvt.u32.u64 %0, t; }"
        : "=r"(a) : "l"(p));
    return a;
}

__device__ __forceinline__ void ldsm4(uint32_t* r, uint32_t addr) {
    asm volatile("ldmatrix.sync.aligned.m8n8.x4.shared.b16 {%0,%1,%2,%3}, [%4];"
                 : "=r"(r[0]), "=r"(r[1]), "=r"(r[2]), "=r"(r[3]) : "r"(addr));
}

// D = A(16x16 bf16) * B(16x8 bf16) + D (f32)
__device__ __forceinline__ void mma16816(float* c, const uint32_t* a,
                                         const uint32_t* b) {
    asm volatile(
        "mma.sync.aligned.m16n8k16.row.col.f32.bf16.bf16.f32 "
        "{%0,%1,%2,%3}, {%4,%5,%6,%7}, {%8,%9}, {%0,%1,%2,%3};"
        : "+f"(c[0]), "+f"(c[1]), "+f"(c[2]), "+f"(c[3])
        : "r"(a[0]), "r"(a[1]), "r"(a[2]), "r"(a[3]), "r"(b[0]), "r"(b[1]));
}

// ============================================================================
// fexp2 — 5-FMA polynomial (avoid quarter-rate MUFU)
// ============================================================================
__device__ __forceinline__ float fexp2(float t) {
    t = fmaxf(t, -126.0f);
    float fi = floorf(t);
    float f  = t - fi;
    float p  = fmaf(f, 1.33335581e-3f, 9.61812910e-3f);
    p = fmaf(p, f, 5.55041087e-2f);
    p = fmaf(p, f, 2.40226507e-1f);
    p = fmaf(p, f, 6.93147181e-1f);
    p = fmaf(p, f, 1.0f);
    return __int_as_float(((int)fi + 127) << 23) * p;
}

__device__ __forceinline__ uint32_t packbf2(__nv_bfloat16 a, __nv_bfloat16 b) {
    __nv_bfloat162 t = __halves2bfloat162(a, b);
    return *reinterpret_cast<uint32_t*>(&t);
}

// ============================================================================
// Prep kernels: fp32 -> (bf16 hi, bf16 lo) splits and transposes
// ============================================================================
__global__ void split_kernel(const float4* __restrict__ in,
                             __nv_bfloat162* __restrict__ hi,
                             __nv_bfloat162* __restrict__ lo, int n4) {
    int i = blockIdx.x * blockDim.x + threadIdx.x;
    if (i >= n4) return;
    float4 v = in[i];
    __nv_bfloat16 h0 = __float2bfloat16(v.x), h1 = __float2bfloat16(v.y);
    __nv_bfloat16 h2 = __float2bfloat16(v.z), h3 = __float2bfloat16(v.w);
    hi[2 * i]     = __halves2bfloat162(h0, h1);
    hi[2 * i + 1] = __halves2bfloat162(h2, h3);
    lo[2 * i]     = __halves2bfloat162(__float2bfloat16(v.x - __bfloat162float(h0)),
                                       __float2bfloat16(v.y - __bfloat162float(h1)));
    lo[2 * i + 1] = __halves2bfloat162(__float2bfloat16(v.z - __bfloat162float(h2)),
                                       __float2bfloat16(v.w - __bfloat162float(h3)));
}

// W[k][n] (512x512) -> Wt[n][k] bf16 hi/lo
__global__ void wt_split_kernel(const float* __restrict__ W,
                                __nv_bfloat16* __restrict__ Wth,
                                __nv_bfloat16* __restrict__ Wtl) {
    __shared__ float ts[32][33];
    int n0 = blockIdx.x * 32, k0 = blockIdx.y * 32;
    ts[threadIdx.y][threadIdx.x] = W[(size_t)(k0 + threadIdx.y) * 512 + n0 + threadIdx.x];
    __syncthreads();
    int n = n0 + threadIdx.y, k = k0 + threadIdx.x;
    float v = ts[threadIdx.x][threadIdx.y];
    __nv_bfloat16 hv = __float2bfloat16(v);
    Wth[(size_t)n * 512 + k] = hv;
    Wtl[(size_t)n * 512 + k] = __float2bfloat16(v - __bfloat162float(hv));
}

// V (bh, l, d) fp32 -> Vt (bh, d, l) bf16 hi/lo
__global__ void vt_split_kernel(const float* __restrict__ V,
                                __nv_bfloat16* __restrict__ Vth,
                                __nv_bfloat16* __restrict__ Vtl) {
    __shared__ float ts[64][65];
    int l0 = blockIdx.x * 64, bh = blockIdx.y;
    const float* Vp = V + (size_t)bh * SEQ * DK;
    for (int i = threadIdx.x; i < 4096; i += 256) {
        int r = i >> 6, c = i & 63;
        ts[r][c] = Vp[(size_t)(l0 + r) * DK + c];
    }
    __syncthreads();
    for (int i = threadIdx.x; i < 4096; i += 256) {
        int d = i >> 6, c = i & 63;
        float v = ts[c][d];
        __nv_bfloat16 hv = __float2bfloat16(v);
        size_t o = ((size_t)bh * DK + d) * SEQ + l0 + c;
        Vth[o] = hv;
        Vtl[o] = __float2bfloat16(v - __bfloat162float(hv));
    }
}

// ============================================================================
// HMMA GEMM: C[8192x512] = A @ Wt^T + bias, bf16x3 split.
// CTA 128x128, BK=32, 256 thr = 8 warps (4x2), warp tile 32x64.
// A smem [m][k] stride 40 bf16; B smem [n][k] stride 40.
// OUTMODE 0: fp32 row-major; 1: bf16 hi/lo head-split; 2: fp32 head-split
// ============================================================================
#define GS 40  // smem row stride (bf16) = 80 bytes

template <int OUTMODE>
__global__ __launch_bounds__(256) void mm_gemm(
    const __nv_bfloat16* __restrict__ Ah, const __nv_bfloat16* __restrict__ Al,
    const __nv_bfloat16* __restrict__ Bth, const __nv_bfloat16* __restrict__ Btl,
    const float* __restrict__ bias,
    float* __restrict__ out_f,
    __nv_bfloat16* __restrict__ out_h, __nv_bfloat16* __restrict__ out_l) {
    __shared__ __align__(16) __nv_bfloat16 sm[4 * 128 * GS];
    __nv_bfloat16* sAh = sm;
    __nv_bfloat16* sAl = sm + 128 * GS;
    __nv_bfloat16* sBh = sm + 2 * 128 * GS;
    __nv_bfloat16* sBl = sm + 3 * 128 * GS;

    const int tid = threadIdx.x, wid = tid >> 5, lane = tid & 31;
    const int wm = wid >> 1, wn = wid & 1;
    const int gr = lane >> 2, gc = lane & 3;
    const int m0 = blockIdx.y * 128, n0 = blockIdx.x * 128;

    // ldmatrix per-lane smem addresses
    const uint32_t sb = smem_to_u32(sm);
    const uint32_t aAh = sb + ((uint32_t)(wm * 32 + (lane & 15)) * GS) * 2 +
                         (((lane >> 4) & 1) << 4);
    const uint32_t aAl = aAh + 128 * GS * 2;
    const uint32_t bRow = (uint32_t)(wn * 64 + (lane & 7) + (((lane >> 4) & 1) << 3));
    const uint32_t aBh = sb + 2u * 128 * GS * 2 + bRow * GS * 2 +
                         (((lane >> 3) & 1) << 4);
    const uint32_t aBl = aBh + 128 * GS * 2;

    float c[2][8][4];
#pragma unroll
    for (int i = 0; i < 2; i++)
#pragma unroll
        for (int j = 0; j < 8; j++)
#pragma unroll
            for (int e = 0; e < 4; e++) c[i][j][e] = 0.0f;

    for (int kc = 0; kc < 16; kc++) {
        const int k0 = kc * 32;
        __syncthreads();
        // load tiles: 512 uint4 per buffer, 2 per thread per buffer
#pragma unroll
        for (int t = 0; t < 2; t++) {
            int i = tid + t * 256;
            int r = i >> 2, j = i & 3;
            int so = r * GS + j * 8;
            size_t ga = (size_t)(m0 + r) * 512 + k0 + j * 8;
            size_t gb = (size_t)(n0 + r) * 512 + k0 + j * 8;
            *(uint4*)(sAh + so) = *(const uint4*)(Ah + ga);
            *(uint4*)(sAl + so) = *(const uint4*)(Al + ga);
            *(uint4*)(sBh + so) = *(const uint4*)(Bth + gb);
            *(uint4*)(sBl + so) = *(const uint4*)(Btl + gb);
        }
        __syncthreads();

#pragma unroll
        for (int ks = 0; ks < 2; ks++) {
            uint32_t ah[2][4], al[2][4];
            ldsm4(ah[0], aAh + ks * 32);
            ldsm4(ah[1], aAh + 16 * GS * 2 + ks * 32);
            ldsm4(al[0], aAl + ks * 32);
            ldsm4(al[1], aAl + 16 * GS * 2 + ks * 32);
#pragma unroll
            for (int nt2 = 0; nt2 < 4; nt2++) {
                uint32_t bh[4], bl[4];
                ldsm4(bh, aBh + nt2 * 16 * GS * 2 + ks * 32);
                ldsm4(bl, aBl + nt2 * 16 * GS * 2 + ks * 32);
#pragma unroll
                for (int q = 0; q < 2; q++) {
                    int nt = nt2 * 2 + q;
#pragma unroll
                    for (int mt = 0; mt < 2; mt++) {
                        mma16816(c[mt][nt], ah[mt], &bh[q * 2]);
                        mma16816(c[mt][nt], al[mt], &bh[q * 2]);
                        mma16816(c[mt][nt], ah[mt], &bl[q * 2]);
                    }
                }
            }
        }
    }

    // Epilogue
#pragma unroll
    for (int mt = 0; mt < 2; mt++) {
#pragma unroll
        for (int half = 0; half < 2; half++) {
            int m = m0 + wm * 32 + mt * 16 + gr + half * 8;
            int bb = m >> 11, l = m & 2047;
#pragma unroll
            for (int nt = 0; nt < 8; nt++) {
                int n = n0 + wn * 64 + nt * 8 + 2 * gc;
                float v0 = c[mt][nt][half * 2 + 0] + bias[n];
                float v1 = c[mt][nt][half * 2 + 1] + bias[n + 1];
                if (OUTMODE == 0) {
                    *(float2*)(out_f + (size_t)m * 512 + n) = make_float2(v0, v1);
                } else if (OUTMODE == 1) {
                    int h = n >> 6, d = n & 63;
                    size_t o = ((size_t)(bb * 8 + h) * SEQ + l) * DK + d;
                    __nv_bfloat16 h0 = __float2bfloat16(v0);
                    __nv_bfloat16 h1 = __float2bfloat16(v1);
                    *(__nv_bfloat162*)(out_h + o) = __halves2bfloat162(h0, h1);
                    *(__nv_bfloat162*)(out_l + o) = __halves2bfloat162(
                        __float2bfloat16(v0 - __bfloat162float(h0)),
                        __float2bfloat16(v1 - __bfloat162float(h1)));
                } else {
                    int h = n >> 6, d = n & 63;
                    *(float2*)(out_f + ((size_t)(bb * 8 + h) * SEQ + l) * DK + d) =
                        make_float2(v0, v1);
                }
            }
        }
    }
}

// ============================================================================
// HMMA flash attention. CTA = 128 q rows x one (b,h); 8 warps x 16 q-rows.
// KV tile 64. S in mma accumulators; softmax in registers (quad shuffles);
// P repacked bf16 hi/lo straight into mma A-fragments (no smem round trip).
// ============================================================================
#define AS 72  // smem row stride (bf16) = 144 bytes
// bf16 offsets
#define O_QH 0
#define O_QL (128 * AS)
#define O_KH (2 * 128 * AS)
#define O_KL (O_KH + 64 * AS)
#define O_VH (O_KL + 64 * AS)
#define O_VL (O_VH + 64 * AS)
#define O_END (O_VL + 64 * AS)               // 36864 bf16
#define A_SMEM (O_END * 2 + 256)             // + mask floats

__global__ __launch_bounds__(256) void mm_attn(
    const __nv_bfloat16* __restrict__ Qh, const __nv_bfloat16* __restrict__ Ql,
    const __nv_bfloat16* __restrict__ Kh, const __nv_bfloat16* __restrict__ Kl,
    const __nv_bfloat16* __restrict__ Vh, const __nv_bfloat16* __restrict__ Vl,
    const int* __restrict__ mask, float* __restrict__ AO) {
    extern __shared__ __align__(16) __nv_bfloat16 smA[];
    float* mkS = (float*)(smA + O_END);

    const int tid = threadIdx.x, wid = tid >> 5, lane = tid & 31;
    const int gr = lane >> 2, gc = lane & 3;
    const int q0 = blockIdx.x * 128;
    const int bh = blockIdx.y, b = bh >> 3, h = bh & 7;

    const __nv_bfloat16* Qhp = Qh + (size_t)bh * SEQ * DK;
    const __nv_bfloat16* Qlp = Ql + (size_t)bh * SEQ * DK;
    const __nv_bfloat16* Khp = Kh + (size_t)bh * SEQ * DK;
    const __nv_bfloat16* Klp = Kl + (size_t)bh * SEQ * DK;
    const __nv_bfloat16* Vhp = Vh + (size_t)bh * DK * SEQ;
    const __nv_bfloat16* Vlp = Vl + (size_t)bh * DK * SEQ;

    // Q tiles once: 128 rows x 64, 8 uint4/thread/buffer
#pragma unroll
    for (int t = 0; t < 4; t++) {
        int i = tid + t * 256;
        int r = i >> 3, j = i & 7;
        int so = r * AS + j * 8;
        size_t ga = (size_t)(q0 + r) * DK + j * 8;
        *(uint4*)(smA + O_QH + so) = *(const uint4*)(Qhp + ga);
        *(uint4*)(smA + O_QL + so) = *(const uint4*)(Qlp + ga);
    }

    const uint32_t sb = smem_to_u32(smA);
    // A-operand (Q): rows w*16 + (lane&15), col-half by lane>>4
    const uint32_t aQh = sb + (uint32_t)(wid * 16 + (lane & 15)) * AS * 2 +
                         (((lane >> 4) & 1) << 4);
    const uint32_t aQl = aQh + O_QL * 2;
    // B-operand rows: (lane&7) + ((lane>>4)&1)*8 ; col-half by lane>>3
    const uint32_t bro = (uint32_t)((lane & 7) + (((lane >> 4) & 1) << 3)) * AS * 2 +
                         (((lane >> 3) & 1) << 4);
    const uint32_t aKh = sb + O_KH * 2 + bro;
    const uint32_t aKl = sb + O_KL * 2 + bro;
    const uint32_t aVh = sb + O_VH * 2 + bro;
    const uint32_t aVl = sb + O_VL * 2 + bro;

    const float L2E = 1.4426950408889634f;
    float m0_ = -1e30f, m1_ = -1e30f, l0_ = 0.0f, l1_ = 0.0f;
    float o[8][4];
#pragma unroll
    for (int j = 0; j < 8; j++)
#pragma unroll
        for (int e = 0; e < 4; e++) o[j][e] = 0.0f;

    for (int kt = 0; kt < SEQ; kt += 64) {
        __syncthreads();
        // load K/V hi/lo tiles + mask
#pragma unroll
        for (int t = 0; t < 2; t++) {
            int i = tid + t * 256;
            int r = i >> 3, j = i & 7;
            int so = r * AS + j * 8;
            size_t gk = (size_t)(kt + r) * DK + j * 8;
            size_t gv = (size_t)r * SEQ + kt + j * 8;
            *(uint4*)(smA + O_KH + so) = *(const uint4*)(Khp + gk);
            *(uint4*)(smA + O_KL + so) = *(const uint4*)(Klp + gk);
            *(uint4*)(smA + O_VH + so) = *(const uint4*)(Vhp + gv);
            *(uint4*)(smA + O_VL + so) = *(const uint4*)(Vlp + gv);
        }
        if (tid < 64) mkS[tid] = (mask[b * SEQ + kt + tid] != 0) ? 1.0f : 0.0f;
        __syncthreads();

        // ---- S = Q @ K^T (bf16x3): warp does 16q x 64k
        float s[8][4];
#pragma unroll
        for (int j = 0; j < 8; j++)
#pragma unroll
            for (int e = 0; e < 4; e++) s[j][e] = 0.0f;
#pragma unroll
        for (int ks = 0; ks < 4; ks++) {
            uint32_t qa[4], ql[4];
            ldsm4(qa, aQh + ks * 32);
            ldsm4(ql, aQl + ks * 32);
#pragma unroll
            for (int nt2 = 0; nt2 < 4; nt2++) {
                uint32_t kh[4], kl[4];
                ldsm4(kh, aKh + nt2 * 16 * AS * 2 + ks * 32);
                ldsm4(kl, aKl + nt2 * 16 * AS * 2 + ks * 32);
#pragma unroll
                for (int q = 0; q < 2; q++) {
                    int nt = nt2 * 2 + q;
                    mma16816(s[nt], qa, &kh[q * 2]);
                    mma16816(s[nt], ql, &kh[q * 2]);
                    mma16816(s[nt], qa, &kl[q * 2]);
                }
            }
        }

        // ---- masked scale + row max (rows r0 = w*16+gr, r1 = r0+8)
        float mx0 = -3.0e38f, mx1 = -3.0e38f;
        float mk[8][2];
#pragma unroll
        for (int nt = 0; nt < 8; nt++) {
            float2 m2 = *(const float2*)&mkS[nt * 8 + 2 * gc];
            mk[nt][0] = m2.x;
            mk[nt][1] = m2.y;
            s[nt][0] = (m2.x != 0.0f) ? s[nt][0] * 0.125f : -3.0e38f;
            s[nt][1] = (m2.y != 0.0f) ? s[nt][1] * 0.125f : -3.0e38f;
            s[nt][2] = (m2.x != 0.0f) ? s[nt][2] * 0.125f : -3.0e38f;
            s[nt][3] = (m2.y != 0.0f) ? s[nt][3] * 0.125f : -3.0e38f;
            mx0 = fmaxf(mx0, fmaxf(s[nt][0], s[nt][1]));
            mx1 = fmaxf(mx1, fmaxf(s[nt][2], s[nt][3]));
        }
        mx0 = fmaxf(mx0, __shfl_xor_sync(0xffffffffu, mx0, 1));
        mx0 = fmaxf(mx0, __shfl_xor_sync(0xffffffffu, mx0, 2));
        mx1 = fmaxf(mx1, __shfl_xor_sync(0xffffffffu, mx1, 1));
        mx1 = fmaxf(mx1, __shfl_xor_sync(0xffffffffu, mx1, 2));
        float mn0 = fmaxf(m0_, mx0), mn1 = fmaxf(m1_, mx1);
        float al0 = fexp2((m0_ - mn0) * L2E), al1 = fexp2((m1_ - mn1) * L2E);
        m0_ = mn0;
        m1_ = mn1;

        // ---- exp, sums, and pack P into A-fragments (hi/lo)
        uint32_t pa_h[4][4], pa_l[4][4];
        float sm0 = 0.0f, sm1 = 0.0f;
#pragma unroll
        for (int nt = 0; nt < 8; nt++) {
            float p0 = fexp2((s[nt][0] - mn0) * L2E) * mk[nt][0];
            float p1 = fexp2((s[nt][1] - mn0) * L2E) * mk[nt][1];
            float p2 = fexp2((s[nt][2] - mn1) * L2E) * mk[nt][0];
            float p3 = fexp2((s[nt][3] - mn1) * L2E) * mk[nt][1];
            sm0 += p0 + p1;
            sm1 += p2 + p3;
            __nv_bfloat16 h0 = __float2bfloat16(p0), h1 = __float2bfloat16(p1);
            __nv_bfloat16 h2 = __float2bfloat16(p2), h3 = __float2bfloat16(p3);
            int kp = nt >> 1, q = nt & 1;
            pa_h[kp][q * 2 + 0] = packbf2(h0, h1);
            pa_h[kp][q * 2 + 1] = packbf2(h2, h3);
            pa_l[kp][q * 2 + 0] =
                packbf2(__float2bfloat16(p0 - __bfloat162float(h0)),
                        __float2bfloat16(p1 - __bfloat162float(h1)));
            pa_l[kp][q * 2 + 1] =
                packbf2(__float2bfloat16(p2 - __bfloat162float(h2)),
                        __float2bfloat16(p3 - __bfloat162float(h3)));
        }
        sm0 += __shfl_xor_sync(0xffffffffu, sm0, 1);
        sm0 += __shfl_xor_sync(0xffffffffu, sm0, 2);
        sm1 += __shfl_xor_sync(0xffffffffu, sm1, 1);
        sm1 += __shfl_xor_sync(0xffffffffu, sm1, 2);
        l0_ = l0_ * al0 + sm0;
        l1_ = l1_ * al1 + sm1;

        // rescale O
#pragma unroll
        for (int j = 0; j < 8; j++) {
            o[j][0] *= al0;
            o[j][1] *= al0;
            o[j][2] *= al1;
            o[j][3] *= al1;
        }

        // ---- O += P @ V (bf16x3)
#pragma unroll
        for (int kp = 0; kp < 4; kp++) {
#pragma unroll
            for (int nt2 = 0; nt2 < 4; nt2++) {
                uint32_t vh[4], vl[4];
                ldsm4(vh, aVh + nt2 * 16 * AS * 2 + kp * 32);
                ldsm4(vl, aVl + nt2 * 16 * AS * 2 + kp * 32);
#pragma unroll
                for (int q = 0; q < 2; q++) {
                    int nt = nt2 * 2 + q;
                    mma16816(o[nt], pa_h[kp], &vh[q * 2]);
                    mma16816(o[nt], pa_l[kp], &vh[q * 2]);
                    mma16816(o[nt], pa_h[kp], &vl[q * 2]);
                }
            }
        }
    }

    // ---- normalize + store (B, L, H*64)
    float inv0 = 1.0f / l0_, inv1 = 1.0f / l1_;
    int r0 = q0 + wid * 16 + gr, r1 = r0 + 8;
    float* p0 = AO + (size_t)(b * SEQ + r0) * D_MODEL + h * DK;
    float* p1 = AO + (size_t)(b * SEQ + r1) * D_MODEL + h * DK;
#pragma unroll
    for (int nt = 0; nt < 8; nt++) {
        int cl = nt * 8 + 2 * gc;
        *(float2*)(p0 + cl) = make_float2(o[nt][0] * inv0, o[nt][1] * inv0);
        *(float2*)(p1 + cl) = make_float2(o[nt][2] * inv1, o[nt][3] * inv1);
    }
}

// ============================================================================
// Launch
// ============================================================================
extern "C" void kernel_launch(void* const* d_in, const int* in_sizes, int n_in,
                              void* d_out, int out_size) {
    const float* query = (const float*)d_in[0];
    const float* key   = (const float*)d_in[1];
    const float* value = (const float*)d_in[2];
    const int*   mask  = (const int*)d_in[3];
    const float* Wq = (const float*)d_in[4];
    const float* bq = (const float*)d_in[5];
    const float* Wk = (const float*)d_in[6];
    const float* bk = (const float*)d_in[7];
    const float* Wv = (const float*)d_in[8];
    const float* bv = (const float*)d_in[9];
    const float* Wo = (const float*)d_in[10];
    const float* bo = (const float*)d_in[11];

    __nv_bfloat16 *Ah, *Al, *Wth, *Wtl, *Qh, *Ql, *Kh, *Kl, *Vth, *Vtl;
    float *Vf, *AO;
    cudaGetSymbolAddress((void**)&Ah, g_Ah);
    cudaGetSymbolAddress((void**)&Al, g_Al);
    cudaGetSymbolAddress((void**)&Wth, g_Wth);
    cudaGetSymbolAddress((void**)&Wtl, g_Wtl);
    cudaGetSymbolAddress((void**)&Qh, g_Qh);
    cudaGetSymbolAddress((void**)&Ql, g_Ql);
    cudaGetSymbolAddress((void**)&Kh, g_Kh);
    cudaGetSymbolAddress((void**)&Kl, g_Kl);
    cudaGetSymbolAddress((void**)&Vf, g_Vf);
    cudaGetSymbolAddress((void**)&Vth, g_Vth);
    cudaGetSymbolAddress((void**)&Vtl, g_Vtl);
    cudaGetSymbolAddress((void**)&AO, g_AO);

    cudaFuncSetAttribute(mm_attn, cudaFuncAttributeMaxDynamicSharedMemorySize,
                         A_SMEM);

    const int N4 = MT * D_MODEL / 4;
    dim3 gW(16, 16), bW(32, 32);
    dim3 gG(4, 64), bG(256);

    // Q projection
    wt_split_kernel<<<gW, bW>>>(Wq, Wth, Wtl);
    split_kernel<<<N4 / 256, 256>>>((const float4*)query, (__nv_bfloat162*)Ah,
                                    (__nv_bfloat162*)Al, N4);
    mm_gemm<1><<<gG, bG>>>(Ah, Al, Wth, Wtl, bq, nullptr, Qh, Ql);
    // K projection
    wt_split_kernel<<<gW, bW>>>(Wk, Wth, Wtl);
    split_kernel<<<N4 / 256, 256>>>((const float4*)key, (__nv_bfloat162*)Ah,
                                    (__nv_bfloat162*)Al, N4);
    mm_gemm<1><<<gG, bG>>>(Ah, Al, Wth, Wtl, bk, nullptr, Kh, Kl);
    // V projection (fp32 head-split, then transpose/split)
    wt_split_kernel<<<gW, bW>>>(Wv, Wth, Wtl);
    split_kernel<<<N4 / 256, 256>>>((const float4*)value, (__nv_bfloat162*)Ah,
                                    (__nv_bfloat162*)Al, N4);
    mm_gemm<2><<<gG, bG>>>(Ah, Al, Wth, Wtl, bv, Vf, nullptr, nullptr);
    vt_split_kernel<<<dim3(SEQ / 64, BH), 256>>>(Vf, Vth, Vtl);

    // Attention
    mm_attn<<<dim3(SEQ / 128, BH), 256, A_SMEM>>>(Qh, Ql, Kh, Kl, Vth, Vtl,
                                                  mask, AO);

    // Output projection
    wt_split_kernel<<<gW, bW>>>(Wo, Wth, Wtl);
    split_kernel<<<N4 / 256, 256>>>((const float4*)AO, (__nv_bfloat162*)Ah,
                                    (__nv_bfloat162*)Al, N4);
    mm_gemm<0><<<gG, bG>>>(Ah, Al, Wth, Wtl, bo, (float*)d_out, nullptr,
                           nullptr);
}

// round 8
// speedup vs baseline: 2.4111x; 1.2398x over previous
#include <cuda_runtime.h>
#include <cuda_bf16.h>
#include <cstdint>

#define NUM_HEADS 8
#define D_MODEL   512
#define DK        64
#define SEQ       2048
#define BATCH     4
#define MT        (BATCH * SEQ)        // 8192
#define BH        (BATCH * NUM_HEADS)  // 32

// ============================================================================
// Scratch (device globals — no allocation allowed)
// ============================================================================
__device__ __align__(16) __nv_bfloat16 g_Ah[3 * MT * D_MODEL];
__device__ __align__(16) __nv_bfloat16 g_Al[3 * MT * D_MODEL];
__device__ __align__(16) __nv_bfloat16 g_Wth[4 * D_MODEL * D_MODEL];
__device__ __align__(16) __nv_bfloat16 g_Wtl[4 * D_MODEL * D_MODEL];
__device__ __align__(16) __nv_bfloat16 g_Qh[BH * SEQ * DK];
__device__ __align__(16) __nv_bfloat16 g_Ql[BH * SEQ * DK];
__device__ __align__(16) __nv_bfloat16 g_Kh[BH * SEQ * DK];
__device__ __align__(16) __nv_bfloat16 g_Kl[BH * SEQ * DK];
__device__ __align__(16) float         g_Vf[BH * SEQ * DK];
__device__ __align__(16) __nv_bfloat16 g_Vth[BH * DK * SEQ];
__device__ __align__(16) __nv_bfloat16 g_Vtl[BH * DK * SEQ];

// ============================================================================
// PTX primitives (all legal at compute_103 baseline)
// ============================================================================
__device__ __forceinline__ uint32_t smem_to_u32(const void* p) {
    uint32_t a;
    asm("{ .reg .u64 t; cvta.to.shared.u64 t, %1; cvt.u32.u64 %0, t; }"
        : "=r"(a) : "l"(p));
    return a;
}

__device__ __forceinline__ void ldsm4(uint32_t* r, uint32_t addr) {
    asm volatile("ldmatrix.sync.aligned.m8n8.x4.shared.b16 {%0,%1,%2,%3}, [%4];"
                 : "=r"(r[0]), "=r"(r[1]), "=r"(r[2]), "=r"(r[3]) : "r"(addr));
}

__device__ __forceinline__ void mma16816(float* c, const uint32_t* a,
                                         const uint32_t* b) {
    asm volatile(
        "mma.sync.aligned.m16n8k16.row.col.f32.bf16.bf16.f32 "
        "{%0,%1,%2,%3}, {%4,%5,%6,%7}, {%8,%9}, {%0,%1,%2,%3};"
        : "+f"(c[0]), "+f"(c[1]), "+f"(c[2]), "+f"(c[3])
        : "r"(a[0]), "r"(a[1]), "r"(a[2]), "r"(a[3]), "r"(b[0]), "r"(b[1]));
}

#define CP16(dst, src) \
    asm volatile("cp.async.cg.shared.global [%0], [%1], 16;" \
                 :: "r"(dst), "l"(src) : "memory")
#define CP_COMMIT() asm volatile("cp.async.commit_group;" ::: "memory")
#define CP_WAIT0()  asm volatile("cp.async.wait_group 0;" ::: "memory")

__device__ __forceinline__ float fexp2(float t) {
    t = fmaxf(t, -126.0f);
    float fi = floorf(t);
    float f  = t - fi;
    float p  = fmaf(f, 1.33335581e-3f, 9.61812910e-3f);
    p = fmaf(p, f, 5.55041087e-2f);
    p = fmaf(p, f, 2.40226507e-1f);
    p = fmaf(p, f, 6.93147181e-1f);
    p = fmaf(p, f, 1.0f);
    return __int_as_float(((int)fi + 127) << 23) * p;
}

__device__ __forceinline__ uint32_t packbf2(__nv_bfloat16 a, __nv_bfloat16 b) {
    __nv_bfloat162 t = __halves2bfloat162(a, b);
    return *reinterpret_cast<uint32_t*>(&t);
}

// ============================================================================
// Prep kernels (batched over z)
// ============================================================================
__global__ void split_b_kernel(const float4* __restrict__ q,
                               const float4* __restrict__ k,
                               const float4* __restrict__ v,
                               __nv_bfloat16* __restrict__ Ah,
                               __nv_bfloat16* __restrict__ Al, int n4) {
    int i = blockIdx.x * blockDim.x + threadIdx.x;
    if (i >= n4) return;
    int z = blockIdx.y;
    const float4* in = (z == 0) ? q : (z == 1) ? k : v;
    __nv_bfloat162* hi = (__nv_bfloat162*)(Ah + (size_t)z * MT * D_MODEL);
    __nv_bfloat162* lo = (__nv_bfloat162*)(Al + (size_t)z * MT * D_MODEL);
    float4 vv = in[i];
    __nv_bfloat16 h0 = __float2bfloat16(vv.x), h1 = __float2bfloat16(vv.y);
    __nv_bfloat16 h2 = __float2bfloat16(vv.z), h3 = __float2bfloat16(vv.w);
    hi[2 * i]     = __halves2bfloat162(h0, h1);
    hi[2 * i + 1] = __halves2bfloat162(h2, h3);
    lo[2 * i]     = __halves2bfloat162(__float2bfloat16(vv.x - __bfloat162float(h0)),
                                       __float2bfloat16(vv.y - __bfloat162float(h1)));
    lo[2 * i + 1] = __halves2bfloat162(__float2bfloat16(vv.z - __bfloat162float(h2)),
                                       __float2bfloat16(vv.w - __bfloat162float(h3)));
}

__global__ void wt_split_b_kernel(const float* __restrict__ W0,
                                  const float* __restrict__ W1,
                                  const float* __restrict__ W2,
                                  const float* __restrict__ W3,
                                  __nv_bfloat16* __restrict__ Wth,
                                  __nv_bfloat16* __restrict__ Wtl) {
    __shared__ float ts[32][33];
    int z = blockIdx.z;
    const float* W = (z == 0) ? W0 : (z == 1) ? W1 : (z == 2) ? W2 : W3;
    __nv_bfloat16* oh = Wth + (size_t)z * D_MODEL * D_MODEL;
    __nv_bfloat16* ol = Wtl + (size_t)z * D_MODEL * D_MODEL;
    int n0 = blockIdx.x * 32, k0 = blockIdx.y * 32;
    ts[threadIdx.y][threadIdx.x] = W[(size_t)(k0 + threadIdx.y) * 512 + n0 + threadIdx.x];
    __syncthreads();
    int n = n0 + threadIdx.y, k = k0 + threadIdx.x;
    float v = ts[threadIdx.x][threadIdx.y];
    __nv_bfloat16 hv = __float2bfloat16(v);
    oh[(size_t)n * 512 + k] = hv;
    ol[(size_t)n * 512 + k] = __float2bfloat16(v - __bfloat162float(hv));
}

__global__ void vt_split_kernel(const float* __restrict__ V,
                                __nv_bfloat16* __restrict__ Vth,
                                __nv_bfloat16* __restrict__ Vtl) {
    __shared__ float ts[64][65];
    int l0 = blockIdx.x * 64, bh = blockIdx.y;
    const float* Vp = V + (size_t)bh * SEQ * DK;
    for (int i = threadIdx.x; i < 4096; i += 256) {
        int r = i >> 6, c = i & 63;
        ts[r][c] = Vp[(size_t)(l0 + r) * DK + c];
    }
    __syncthreads();
    for (int i = threadIdx.x; i < 4096; i += 256) {
        int d = i >> 6, c = i & 63;
        float v = ts[c][d];
        __nv_bfloat16 hv = __float2bfloat16(v);
        size_t o = ((size_t)bh * DK + d) * SEQ + l0 + c;
        Vth[o] = hv;
        Vtl[o] = __float2bfloat16(v - __bfloat162float(hv));
    }
}

// ============================================================================
// HMMA GEMM (cp.async double-buffered): C[8192x512] = A @ Wt^T + bias, bf16x3.
// CTA 128x128, BK=32, 8 warps (4x2), warp tile 32x64.
// z = blockIdx.z + zofs: 0=Q, 1=K (bf16 hi/lo head-split), 2=V (f32 head-split),
// 3 = output projection (f32 row-major to d_out).
// ============================================================================
#define GRB    80      // smem row bytes (40 bf16)
#define GTILE  10240   // 128 rows
#define GSTAGE 40960   // 4 tiles
#define G_SMEM (2 * GSTAGE)

__global__ __launch_bounds__(256) void mm_gemm(
    const __nv_bfloat16* __restrict__ Ahb, const __nv_bfloat16* __restrict__ Alb,
    const __nv_bfloat16* __restrict__ Wthb, const __nv_bfloat16* __restrict__ Wtlb,
    const float* __restrict__ bq, const float* __restrict__ bk,
    const float* __restrict__ bv, const float* __restrict__ bo,
    __nv_bfloat16* __restrict__ Qh, __nv_bfloat16* __restrict__ Ql,
    __nv_bfloat16* __restrict__ Kh, __nv_bfloat16* __restrict__ Kl,
    float* __restrict__ Vf, float* __restrict__ dout, int zofs) {
    extern __shared__ __align__(16) char smg[];
    const int tid = threadIdx.x, wid = tid >> 5, lane = tid & 31;
    const int wm = wid >> 1, wn = wid & 1;
    const int gr = lane >> 2, gc = lane & 3;
    const int m0 = blockIdx.y * 128, n0 = blockIdx.x * 128;
    const int z = blockIdx.z + zofs;

    const __nv_bfloat16* Ah = Ahb + (size_t)((z == 3) ? 0 : z) * MT * D_MODEL;
    const __nv_bfloat16* Al = Alb + (size_t)((z == 3) ? 0 : z) * MT * D_MODEL;
    const __nv_bfloat16* Bh = Wthb + (size_t)z * D_MODEL * D_MODEL;
    const __nv_bfloat16* Bl = Wtlb + (size_t)z * D_MODEL * D_MODEL;
    const float* bias = (z == 0) ? bq : (z == 1) ? bk : (z == 2) ? bv : bo;

    const uint32_t sb = smem_to_u32(smg);
    // ldmatrix lane addresses (relative to stage base)
    const uint32_t rAh = (uint32_t)(wm * 32 + (lane & 15)) * GRB + (((lane >> 4) & 1) << 4);
    const uint32_t rBh = 2u * GTILE +
        (uint32_t)(wn * 64 + (lane & 7) + (((lane >> 4) & 1) << 3)) * GRB +
        (((lane >> 3) & 1) << 4);

    // cp.async lane chunks
    const int pr = tid >> 2, pj = tid & 3;
    const uint32_t poff = (uint32_t)pr * GRB + pj * 16;

    float c[2][8][4];
#pragma unroll
    for (int i = 0; i < 2; i++)
#pragma unroll
        for (int j = 0; j < 8; j++)
#pragma unroll
            for (int e = 0; e < 4; e++) c[i][j][e] = 0.0f;

    // prefetch kc=0 into stage 0
    {
        const int k0 = 0;
#pragma unroll
        for (int t = 0; t < 2; t++) {
            int r = pr + t * 64;
            uint32_t d = sb + poff + (uint32_t)t * 64 * GRB;
            size_t ga = (size_t)(m0 + r) * 512 + k0 + pj * 8;
            size_t gb = (size_t)(n0 + r) * 512 + k0 + pj * 8;
            CP16(d, Ah + ga);
            CP16(d + GTILE, Al + ga);
            CP16(d + 2 * GTILE, Bh + gb);
            CP16(d + 3 * GTILE, Bl + gb);
        }
        CP_COMMIT();
    }

    for (int kc = 0; kc < 16; kc++) {
        const uint32_t stg = sb + (uint32_t)(kc & 1) * GSTAGE;
        CP_WAIT0();
        __syncthreads();
        if (kc < 15) {
            const int k0 = (kc + 1) * 32;
            const uint32_t nstg = sb + (uint32_t)((kc + 1) & 1) * GSTAGE;
#pragma unroll
            for (int t = 0; t < 2; t++) {
                int r = pr + t * 64;
                uint32_t d = nstg + poff + (uint32_t)t * 64 * GRB;
                size_t ga = (size_t)(m0 + r) * 512 + k0 + pj * 8;
                size_t gb = (size_t)(n0 + r) * 512 + k0 + pj * 8;
                CP16(d, Ah + ga);
                CP16(d + GTILE, Al + ga);
                CP16(d + 2 * GTILE, Bh + gb);
                CP16(d + 3 * GTILE, Bl + gb);
            }
            CP_COMMIT();
        }

        const uint32_t aAh = stg + rAh, aBh = stg + rBh;
#pragma unroll
        for (int ks = 0; ks < 2; ks++) {
            uint32_t ah[2][4], al[2][4];
            ldsm4(ah[0], aAh + ks * 32);
            ldsm4(ah[1], aAh + 16 * GRB + ks * 32);
            ldsm4(al[0], aAh + GTILE + ks * 32);
            ldsm4(al[1], aAh + GTILE + 16 * GRB + ks * 32);
#pragma unroll
            for (int nt2 = 0; nt2 < 4; nt2++) {
                uint32_t bh[4], bl[4];
                ldsm4(bh, aBh + nt2 * 16 * GRB + ks * 32);
                ldsm4(bl, aBh + GTILE + nt2 * 16 * GRB + ks * 32);
#pragma unroll
                for (int q = 0; q < 2; q++) {
                    int nt = nt2 * 2 + q;
#pragma unroll
                    for (int mt = 0; mt < 2; mt++) {
                        mma16816(c[mt][nt], ah[mt], &bh[q * 2]);
                        mma16816(c[mt][nt], al[mt], &bh[q * 2]);
                        mma16816(c[mt][nt], ah[mt], &bl[q * 2]);
                    }
                }
            }
        }
    }

    // Epilogue
#pragma unroll
    for (int mt = 0; mt < 2; mt++) {
#pragma unroll
        for (int half = 0; half < 2; half++) {
            int m = m0 + wm * 32 + mt * 16 + gr + half * 8;
            int bb = m >> 11, l = m & 2047;
#pragma unroll
            for (int nt = 0; nt < 8; nt++) {
                int n = n0 + wn * 64 + nt * 8 + 2 * gc;
                float v0 = c[mt][nt][half * 2 + 0] + bias[n];
                float v1 = c[mt][nt][half * 2 + 1] + bias[n + 1];
                if (z == 3) {
                    *(float2*)(dout + (size_t)m * 512 + n) = make_float2(v0, v1);
                } else if (z == 2) {
                    int h = n >> 6, d = n & 63;
                    *(float2*)(Vf + ((size_t)(bb * 8 + h) * SEQ + l) * DK + d) =
                        make_float2(v0, v1);
                } else {
                    int h = n >> 6, d = n & 63;
                    size_t o = ((size_t)(bb * 8 + h) * SEQ + l) * DK + d;
                    __nv_bfloat16 h0 = __float2bfloat16(v0);
                    __nv_bfloat16 h1 = __float2bfloat16(v1);
                    __nv_bfloat16* oh = (z == 0) ? Qh : Kh;
                    __nv_bfloat16* ol = (z == 0) ? Ql : Kl;
                    *(__nv_bfloat162*)(oh + o) = __halves2bfloat162(h0, h1);
                    *(__nv_bfloat162*)(ol + o) = __halves2bfloat162(
                        __float2bfloat16(v0 - __bfloat162float(h0)),
                        __float2bfloat16(v1 - __bfloat162float(h1)));
                }
            }
        }
    }
}

// ============================================================================
// HMMA flash attention, cp.async double-buffered KV pipeline.
// CTA = 128 q rows x one (b,h); 8 warps x 16 q-rows; KV tile 64.
// Q fragments cached in registers (staged via buffer 1, then recycled).
// Epilogue writes bf16 hi/lo split directly (input of output projection).
// ============================================================================
#define ARB   144                 // smem row bytes (72 bf16)
#define ATILE (256 * ARB)         // one stage: KH(64) KL(64) VH(64) VL(64) rows
#define A_SMEM (2 * ATILE + 512)  // + int mask[2][64]

__global__ __launch_bounds__(256) void mm_attn(
    const __nv_bfloat16* __restrict__ Qh, const __nv_bfloat16* __restrict__ Ql,
    const __nv_bfloat16* __restrict__ Kh, const __nv_bfloat16* __restrict__ Kl,
    const __nv_bfloat16* __restrict__ Vh, const __nv_bfloat16* __restrict__ Vl,
    const int* __restrict__ mask,
    __nv_bfloat16* __restrict__ OutH, __nv_bfloat16* __restrict__ OutL) {
    extern __shared__ __align__(16) char smA[];
    int* mks = (int*)(smA + 2 * ATILE);

    const int tid = threadIdx.x, wid = tid >> 5, lane = tid & 31;
    const int gr = lane >> 2, gc = lane & 3;
    const int q0 = blockIdx.x * 128;
    const int bh = blockIdx.y, b = bh >> 3, h = bh & 7;

    const __nv_bfloat16* Qhp = Qh + (size_t)bh * SEQ * DK;
    const __nv_bfloat16* Qlp = Ql + (size_t)bh * SEQ * DK;
    const __nv_bfloat16* Khp = Kh + (size_t)bh * SEQ * DK;
    const __nv_bfloat16* Klp = Kl + (size_t)bh * SEQ * DK;
    const __nv_bfloat16* Vhp = Vh + (size_t)bh * DK * SEQ;
    const __nv_bfloat16* Vlp = Vl + (size_t)bh * DK * SEQ;
    const int* mkp = mask + b * SEQ;

    const uint32_t sb = smem_to_u32(smA);
    const uint32_t mbase = sb + 2 * ATILE;

    // cp.async lane chunks for KV tiles
    const int pr = tid >> 3, pj = tid & 7;

    // ---- prefetch KV tile 0 into stage 0
    {
#pragma unroll
        for (int t = 0; t < 2; t++) {
            int r = pr + t * 32;
            uint32_t d = sb + (uint32_t)r * ARB + pj * 16;
            size_t gk = (size_t)r * DK + pj * 8;
            size_t gv = (size_t)r * SEQ + pj * 8;
            CP16(d, Khp + gk);
            CP16(d + 64 * ARB, Klp + gk);
            CP16(d + 128 * ARB, Vhp + gv);
            CP16(d + 192 * ARB, Vlp + gv);
        }
        if (tid < 16) CP16(mbase + tid * 16, mkp + tid * 4);
        CP_COMMIT();
    }

    // ---- stage Q into buffer 1 (plain stores), load fragments, recycle buffer
#pragma unroll
    for (int t = 0; t < 4; t++) {
        int i = tid + t * 256;
        int r = i >> 3, j = i & 7;
        uint32_t d = sb + ATILE + (uint32_t)r * ARB + j * 16;
        *(uint4*)(uintptr_t)0;  // placeholder removed below
        (void)d;
    }
    // (actual Q staging — uint4 global loads + smem stores)
#pragma unroll
    for (int t = 0; t < 4; t++) {
        int i = tid + t * 256;
        int r = i >> 3, j = i & 7;
        char* dsth = smA + ATILE + (size_t)r * ARB + j * 16;
        char* dstl = smA + ATILE + (size_t)(128 + r) * ARB + j * 16;
        *(uint4*)dsth = *(const uint4*)(Qhp + (size_t)(q0 + r) * DK + j * 8);
        *(uint4*)dstl = *(const uint4*)(Qlp + (size_t)(q0 + r) * DK + j * 8);
    }
    __syncthreads();

    uint32_t qh[4][4], ql[4][4];
    {
        const uint32_t aQ = sb + ATILE +
            (uint32_t)(wid * 16 + (lane & 15)) * ARB + (((lane >> 4) & 1) << 4);
#pragma unroll
        for (int ks = 0; ks < 4; ks++) {
            ldsm4(qh[ks], aQ + ks * 32);
            ldsm4(ql[ks], aQ + 128 * ARB + ks * 32);
        }
    }
    CP_WAIT0();
    __syncthreads();  // Q frags read everywhere; stage 0 KV visible; buffer 1 free

    const uint32_t bro = (uint32_t)((lane & 7) + (((lane >> 4) & 1) << 3)) * ARB +
                         (((lane >> 3) & 1) << 4);

    const float L2E = 1.4426950408889634f;
    float m0_ = -1e30f, m1_ = -1e30f, l0_ = 0.0f, l1_ = 0.0f;
    float o[8][4];
#pragma unroll
    for (int j = 0; j < 8; j++)
#pragma unroll
        for (int e = 0; e < 4; e++) o[j][e] = 0.0f;

    for (int it = 0; it < 32; it++) {
        const int cur = it & 1;
        const uint32_t stg = sb + (uint32_t)cur * ATILE;
        const int* mcur = mks + cur * 64;

        if (it > 0) {
            CP_WAIT0();
            __syncthreads();
        }
        if (it < 31) {
            const int ktn = (it + 1) * 64;
            const uint32_t nstg = sb + (uint32_t)(1 - cur) * ATILE;
#pragma unroll
            for (int t = 0; t < 2; t++) {
                int r = pr + t * 32;
                uint32_t d = nstg + (uint32_t)r * ARB + pj * 16;
                size_t gk = (size_t)(ktn + r) * DK + pj * 8;
                size_t gv = (size_t)r * SEQ + ktn + pj * 8;
                CP16(d, Khp + gk);
                CP16(d + 64 * ARB, Klp + gk);
                CP16(d + 128 * ARB, Vhp + gv);
                CP16(d + 192 * ARB, Vlp + gv);
            }
            if (tid < 16)
                CP16(mbase + (1 - cur) * 256 + tid * 16, mkp + ktn + tid * 4);
            CP_COMMIT();
        }

        // ---- S = Q @ K^T (bf16x3)
        float s[8][4];
#pragma unroll
        for (int j = 0; j < 8; j++)
#pragma unroll
            for (int e = 0; e < 4; e++) s[j][e] = 0.0f;
        const uint32_t aKh = stg + bro, aKl = stg + 64 * ARB + bro;
#pragma unroll
        for (int ks = 0; ks < 4; ks++) {
#pragma unroll
            for (int nt2 = 0; nt2 < 4; nt2++) {
                uint32_t kh[4], kl[4];
                ldsm4(kh, aKh + nt2 * 16 * ARB + ks * 32);
                ldsm4(kl, aKl + nt2 * 16 * ARB + ks * 32);
#pragma unroll
                for (int q = 0; q < 2; q++) {
                    int nt = nt2 * 2 + q;
                    mma16816(s[nt], qh[ks], &kh[q * 2]);
                    mma16816(s[nt], ql[ks], &kh[q * 2]);
                    mma16816(s[nt], qh[ks], &kl[q * 2]);
                }
            }
        }

        // ---- masked scale + row max
        float mx0 = -3.0e38f, mx1 = -3.0e38f;
        float mk[8][2];
#pragma unroll
        for (int nt = 0; nt < 8; nt++) {
            int2 mi = *(const int2*)&mcur[nt * 8 + 2 * gc];
            mk[nt][0] = (mi.x != 0) ? 1.0f : 0.0f;
            mk[nt][1] = (mi.y != 0) ? 1.0f : 0.0f;
            s[nt][0] = (mi.x != 0) ? s[nt][0] * 0.125f : -3.0e38f;
            s[nt][1] = (mi.y != 0) ? s[nt][1] * 0.125f : -3.0e38f;
            s[nt][2] = (mi.x != 0) ? s[nt][2] * 0.125f : -3.0e38f;
            s[nt][3] = (mi.y != 0) ? s[nt][3] * 0.125f : -3.0e38f;
            mx0 = fmaxf(mx0, fmaxf(s[nt][0], s[nt][1]));
            mx1 = fmaxf(mx1, fmaxf(s[nt][2], s[nt][3]));
        }
        mx0 = fmaxf(mx0, __shfl_xor_sync(0xffffffffu, mx0, 1));
        mx0 = fmaxf(mx0, __shfl_xor_sync(0xffffffffu, mx0, 2));
        mx1 = fmaxf(mx1, __shfl_xor_sync(0xffffffffu, mx1, 1));
        mx1 = fmaxf(mx1, __shfl_xor_sync(0xffffffffu, mx1, 2));
        float mn0 = fmaxf(m0_, mx0), mn1 = fmaxf(m1_, mx1);
        float al0 = fexp2((m0_ - mn0) * L2E), al1 = fexp2((m1_ - mn1) * L2E);
        m0_ = mn0;
        m1_ = mn1;

        // ---- exp, sums, pack P into mma A-fragments (hi/lo)
        uint32_t pa_h[4][4], pa_l[4][4];
        float sm0 = 0.0f, sm1 = 0.0f;
#pragma unroll
        for (int nt = 0; nt < 8; nt++) {
            float p0 = fexp2((s[nt][0] - mn0) * L2E) * mk[nt][0];
            float p1 = fexp2((s[nt][1] - mn0) * L2E) * mk[nt][1];
            float p2 = fexp2((s[nt][2] - mn1) * L2E) * mk[nt][0];
            float p3 = fexp2((s[nt][3] - mn1) * L2E) * mk[nt][1];
            sm0 += p0 + p1;
            sm1 += p2 + p3;
            __nv_bfloat16 h0 = __float2bfloat16(p0), h1 = __float2bfloat16(p1);
            __nv_bfloat16 h2 = __float2bfloat16(p2), h3 = __float2bfloat16(p3);
            int kp = nt >> 1, q = nt & 1;
            pa_h[kp][q * 2 + 0] = packbf2(h0, h1);
            pa_h[kp][q * 2 + 1] = packbf2(h2, h3);
            pa_l[kp][q * 2 + 0] =
                packbf2(__float2bfloat16(p0 - __bfloat162float(h0)),
                        __float2bfloat16(p1 - __bfloat162float(h1)));
            pa_l[kp][q * 2 + 1] =
                packbf2(__float2bfloat16(p2 - __bfloat162float(h2)),
                        __float2bfloat16(p3 - __bfloat162float(h3)));
        }
        sm0 += __shfl_xor_sync(0xffffffffu, sm0, 1);
        sm0 += __shfl_xor_sync(0xffffffffu, sm0, 2);
        sm1 += __shfl_xor_sync(0xffffffffu, sm1, 1);
        sm1 += __shfl_xor_sync(0xffffffffu, sm1, 2);
        l0_ = l0_ * al0 + sm0;
        l1_ = l1_ * al1 + sm1;

#pragma unroll
        for (int j = 0; j < 8; j++) {
            o[j][0] *= al0;
            o[j][1] *= al0;
            o[j][2] *= al1;
            o[j][3] *= al1;
        }

        // ---- O += P @ V (bf16x3)
        const uint32_t aVh = stg + 128 * ARB + bro, aVl = stg + 192 * ARB + bro;
#pragma unroll
        for (int kp = 0; kp < 4; kp++) {
#pragma unroll
            for (int nt2 = 0; nt2 < 4; nt2++) {
                uint32_t vh[4], vl[4];
                ldsm4(vh, aVh + nt2 * 16 * ARB + kp * 32);
                ldsm4(vl, aVl + nt2 * 16 * ARB + kp * 32);
#pragma unroll
                for (int q = 0; q < 2; q++) {
                    int nt = nt2 * 2 + q;
                    mma16816(o[nt], pa_h[kp], &vh[q * 2]);
                    mma16816(o[nt], pa_l[kp], &vh[q * 2]);
                    mma16816(o[nt], pa_h[kp], &vl[q * 2]);
                }
            }
        }
    }

    // ---- normalize + store bf16 hi/lo split at (B, L, H*64) for out-proj
    float inv0 = 1.0f / l0_, inv1 = 1.0f / l1_;
    int r0 = q0 + wid * 16 + gr, r1 = r0 + 8;
    size_t base0 = (size_t)(b * SEQ + r0) * D_MODEL + h * DK;
    size_t base1 = (size_t)(b * SEQ + r1) * D_MODEL + h * DK;
#pragma unroll
    for (int nt = 0; nt < 8; nt++) {
        int cl = nt * 8 + 2 * gc;
        float v0 = o[nt][0] * inv0, v1 = o[nt][1] * inv0;
        float v2 = o[nt][2] * inv1, v3 = o[nt][3] * inv1;
        __nv_bfloat16 h0 = __float2bfloat16(v0), h1 = __float2bfloat16(v1);
        __nv_bfloat16 h2 = __float2bfloat16(v2), h3 = __float2bfloat16(v3);
        *(__nv_bfloat162*)(OutH + base0 + cl) = __halves2bfloat162(h0, h1);
        *(__nv_bfloat162*)(OutL + base0 + cl) = __halves2bfloat162(
            __float2bfloat16(v0 - __bfloat162float(h0)),
            __float2bfloat16(v1 - __bfloat162float(h1)));
        *(__nv_bfloat162*)(OutH + base1 + cl) = __halves2bfloat162(h2, h3);
        *(__nv_bfloat162*)(OutL + base1 + cl) = __halves2bfloat162(
            __float2bfloat16(v2 - __bfloat162float(h2)),
            __float2bfloat16(v3 - __bfloat162float(h3)));
    }
}

// ============================================================================
// Launch: 6 kernels total
// ============================================================================
extern "C" void kernel_launch(void* const* d_in, const int* in_sizes, int n_in,
                              void* d_out, int out_size) {
    const float* query = (const float*)d_in[0];
    const float* key   = (const float*)d_in[1];
    const float* value = (const float*)d_in[2];
    const int*   mask  = (const int*)d_in[3];
    const float* Wq = (const float*)d_in[4];
    const float* bq = (const float*)d_in[5];
    const float* Wk = (const float*)d_in[6];
    const float* bk = (const float*)d_in[7];
    const float* Wv = (const float*)d_in[8];
    const float* bv = (const float*)d_in[9];
    const float* Wo = (const float*)d_in[10];
    const float* bo = (const float*)d_in[11];

    __nv_bfloat16 *Ah, *Al, *Wth, *Wtl, *Qh, *Ql, *Kh, *Kl, *Vth, *Vtl;
    float *Vf;
    cudaGetSymbolAddress((void**)&Ah, g_Ah);
    cudaGetSymbolAddress((void**)&Al, g_Al);
    cudaGetSymbolAddress((void**)&Wth, g_Wth);
    cudaGetSymbolAddress((void**)&Wtl, g_Wtl);
    cudaGetSymbolAddress((void**)&Qh, g_Qh);
    cudaGetSymbolAddress((void**)&Ql, g_Ql);
    cudaGetSymbolAddress((void**)&Kh, g_Kh);
    cudaGetSymbolAddress((void**)&Kl, g_Kl);
    cudaGetSymbolAddress((void**)&Vf, g_Vf);
    cudaGetSymbolAddress((void**)&Vth, g_Vth);
    cudaGetSymbolAddress((void**)&Vtl, g_Vtl);

    cudaFuncSetAttribute(mm_gemm, cudaFuncAttributeMaxDynamicSharedMemorySize,
                         G_SMEM);
    cudaFuncSetAttribute(mm_attn, cudaFuncAttributeMaxDynamicSharedMemorySize,
                         A_SMEM);

    const int N4 = MT * D_MODEL / 4;

    // 1. all 4 weight transposes/splits
    wt_split_b_kernel<<<dim3(16, 16, 4), dim3(32, 32)>>>(Wq, Wk, Wv, Wo, Wth, Wtl);
    // 2. query/key/value input splits
    split_b_kernel<<<dim3(N4 / 256, 3), 256>>>((const float4*)query,
                                               (const float4*)key,
                                               (const float4*)value, Ah, Al, N4);
    // 3. Q/K/V projections (one launch, z-batched)
    mm_gemm<<<dim3(4, 64, 3), 256, G_SMEM>>>(Ah, Al, Wth, Wtl, bq, bk, bv, bo,
                                             Qh, Ql, Kh, Kl, Vf, nullptr, 0);
    // 4. V transpose + split
    vt_split_kernel<<<dim3(SEQ / 64, BH), 256>>>(Vf, Vth, Vtl);
    // 5. attention (writes hi/lo split directly into Ah/Al slot 0)
    mm_attn<<<dim3(SEQ / 128, BH), 256, A_SMEM>>>(Qh, Ql, Kh, Kl, Vth, Vtl,
                                                  mask, Ah, Al);
    // 6. output projection
    mm_gemm<<<dim3(4, 64, 1), 256, G_SMEM>>>(Ah, Al, Wth, Wtl, bq, bk, bv, bo,
                                             nullptr, nullptr, nullptr, nullptr,
                                             nullptr, (float*)d_out, 3);
}

// round 9
// speedup vs baseline: 3.3634x; 1.3950x over previous
#include <cuda_runtime.h>
#include <cuda_bf16.h>
#include <cstdint>

#define NUM_HEADS 8
#define D_MODEL   512
#define DK        64
#define SEQ       2048
#define BATCH     4
#define MT        (BATCH * SEQ)        // 8192
#define BH        (BATCH * NUM_HEADS)  // 32

// ============================================================================
// Scratch (device globals — no allocation allowed)
// ============================================================================
__device__ __align__(16) __nv_bfloat16 g_Ah[3 * MT * D_MODEL];
__device__ __align__(16) __nv_bfloat16 g_Al[3 * MT * D_MODEL];
__device__ __align__(16) __nv_bfloat16 g_Wth[4 * D_MODEL * D_MODEL];
__device__ __align__(16) __nv_bfloat16 g_Wtl[4 * D_MODEL * D_MODEL];
__device__ __align__(16) __nv_bfloat16 g_Qh[BH * SEQ * DK];
__device__ __align__(16) __nv_bfloat16 g_Ql[BH * SEQ * DK];
__device__ __align__(16) __nv_bfloat16 g_Kh[BH * SEQ * DK];
__device__ __align__(16) __nv_bfloat16 g_Kl[BH * SEQ * DK];
__device__ __align__(16) __nv_bfloat16 g_Khc[BH * SEQ * DK];  // compacted K hi
__device__ __align__(16) __nv_bfloat16 g_Klc[BH * SEQ * DK];  // compacted K lo
__device__ __align__(16) float         g_Vf[BH * SEQ * DK];
__device__ __align__(16) __nv_bfloat16 g_Vth[BH * DK * SEQ];  // compacted V^T hi
__device__ __align__(16) __nv_bfloat16 g_Vtl[BH * DK * SEQ];  // compacted V^T lo
__device__ int g_idx[BATCH * SEQ];
__device__ int g_nk[BATCH];

// ============================================================================
// PTX primitives (all legal at compute_103 baseline)
// ============================================================================
__device__ __forceinline__ uint32_t smem_to_u32(const void* p) {
    uint32_t a;
    asm("{ .reg .u64 t; cvta.to.shared.u64 t, %1; cvt.u32.u64 %0, t; }"
        : "=r"(a) : "l"(p));
    return a;
}

__device__ __forceinline__ void ldsm4(uint32_t* r, uint32_t addr) {
    asm volatile("ldmatrix.sync.aligned.m8n8.x4.shared.b16 {%0,%1,%2,%3}, [%4];"
                 : "=r"(r[0]), "=r"(r[1]), "=r"(r[2]), "=r"(r[3]) : "r"(addr));
}

__device__ __forceinline__ void mma16816(float* c, const uint32_t* a,
                                         const uint32_t* b) {
    asm volatile(
        "mma.sync.aligned.m16n8k16.row.col.f32.bf16.bf16.f32 "
        "{%0,%1,%2,%3}, {%4,%5,%6,%7}, {%8,%9}, {%0,%1,%2,%3};"
        : "+f"(c[0]), "+f"(c[1]), "+f"(c[2]), "+f"(c[3])
        : "r"(a[0]), "r"(a[1]), "r"(a[2]), "r"(a[3]), "r"(b[0]), "r"(b[1]));
}

#define CP16(dst, src) \
    asm volatile("cp.async.cg.shared.global [%0], [%1], 16;" \
                 :: "r"(dst), "l"(src) : "memory")
#define CP_COMMIT() asm volatile("cp.async.commit_group;" ::: "memory")
#define CP_WAIT0()  asm volatile("cp.async.wait_group 0;" ::: "memory")

__device__ __forceinline__ float fexp2(float t) {
    t = fmaxf(t, -126.0f);
    float fi = floorf(t);
    float f  = t - fi;
    float p  = fmaf(f, 1.33335581e-3f, 9.61812910e-3f);
    p = fmaf(p, f, 5.55041087e-2f);
    p = fmaf(p, f, 2.40226507e-1f);
    p = fmaf(p, f, 6.93147181e-1f);
    p = fmaf(p, f, 1.0f);
    return __int_as_float(((int)fi + 127) << 23) * p;
}

__device__ __forceinline__ uint32_t packbf2(__nv_bfloat16 a, __nv_bfloat16 b) {
    __nv_bfloat162 t = __halves2bfloat162(a, b);
    return *reinterpret_cast<uint32_t*>(&t);
}

// ============================================================================
// Mask prefix scan: per batch, build compacted index list + count
// ============================================================================
__global__ __launch_bounds__(1024) void mask_scan_kernel(
    const int* __restrict__ mask, int* __restrict__ idx, int* __restrict__ nk) {
    const int b = blockIdx.x, tid = threadIdx.x;
    const int lane = tid & 31, w = tid >> 5;
    const int* mp = mask + b * SEQ;
    int e0 = (mp[2 * tid] != 0), e1 = (mp[2 * tid + 1] != 0);
    int tsum = e0 + e1;
    int v = tsum;
#pragma unroll
    for (int o = 1; o < 32; o <<= 1) {
        int u = __shfl_up_sync(0xffffffffu, v, o);
        if (lane >= o) v += u;
    }
    __shared__ int ws[32];
    if (lane == 31) ws[w] = v;
    __syncthreads();
    if (w == 0) {
        int x = ws[lane];
#pragma unroll
        for (int o = 1; o < 32; o <<= 1) {
            int u = __shfl_up_sync(0xffffffffu, x, o);
            if (lane >= o) x += u;
        }
        ws[lane] = x;
    }
    __syncthreads();
    int base = ((w > 0) ? ws[w - 1] : 0) + (v - tsum);
    if (e0) idx[b * SEQ + base] = 2 * tid;
    if (e1) idx[b * SEQ + base + e0] = 2 * tid + 1;
    if (tid == 0) nk[b] = ws[31];
}

// ============================================================================
// KV gather: pack unmasked K rows (hi/lo) densely; gather+transpose+split V.
// grid (SEQ/64, BH), 256 threads. Pads last partial tile with zeros.
// ============================================================================
__global__ __launch_bounds__(256) void kv_gather_kernel(
    const __nv_bfloat16* __restrict__ Kh, const __nv_bfloat16* __restrict__ Kl,
    const float* __restrict__ Vf, const int* __restrict__ idx,
    const int* __restrict__ nk,
    __nv_bfloat16* __restrict__ Khc, __nv_bfloat16* __restrict__ Klc,
    __nv_bfloat16* __restrict__ Vth, __nv_bfloat16* __restrict__ Vtl) {
    const int t = blockIdx.x, bh = blockIdx.y, b = bh >> 3;
    const int tid = threadIdx.x;
    const int n = nk[b];
    const int j0 = t * 64;
    if (j0 >= ((n + 63) & ~63)) return;  // tile never read by attention
    const int* idxb = idx + b * SEQ;

    // ---- K gather (hi & lo): 64 rows x 128B each
    const uint4 z4 = make_uint4(0, 0, 0, 0);
#pragma unroll
    for (int t2 = 0; t2 < 2; t2++) {
        int i = tid + t2 * 256;
        int r = i >> 3, j = i & 7;
        int jj = j0 + r;
        int row = (jj < n) ? idxb[jj] : -1;
        size_t src = ((size_t)bh * SEQ + row) * DK + j * 8;
        size_t dst = ((size_t)bh * SEQ + jj) * DK + j * 8;
        *(uint4*)(Khc + dst) = (row >= 0) ? *(const uint4*)(Kh + src) : z4;
        *(uint4*)(Klc + dst) = (row >= 0) ? *(const uint4*)(Kl + src) : z4;
    }

    // ---- V gather + transpose + split
    __shared__ float ts[64][65];
    for (int i = tid; i < 4096; i += 256) {
        int r = i >> 6, c = i & 63;
        int jj = j0 + r;
        int row = (jj < n) ? idxb[jj] : -1;
        ts[r][c] = (row >= 0) ? Vf[((size_t)bh * SEQ + row) * DK + c] : 0.0f;
    }
    __syncthreads();
    for (int i = tid; i < 4096; i += 256) {
        int d = i >> 6, c = i & 63;
        float v = ts[c][d];
        __nv_bfloat16 hv = __float2bfloat16(v);
        size_t o = ((size_t)bh * DK + d) * SEQ + j0 + c;
        Vth[o] = hv;
        Vtl[o] = __float2bfloat16(v - __bfloat162float(hv));
    }
}

// ============================================================================
// Prep kernels (batched over z)
// ============================================================================
__global__ void split_b_kernel(const float4* __restrict__ q,
                               const float4* __restrict__ k,
                               const float4* __restrict__ v,
                               __nv_bfloat16* __restrict__ Ah,
                               __nv_bfloat16* __restrict__ Al, int n4) {
    int i = blockIdx.x * blockDim.x + threadIdx.x;
    if (i >= n4) return;
    int z = blockIdx.y;
    const float4* in = (z == 0) ? q : (z == 1) ? k : v;
    __nv_bfloat162* hi = (__nv_bfloat162*)(Ah + (size_t)z * MT * D_MODEL);
    __nv_bfloat162* lo = (__nv_bfloat162*)(Al + (size_t)z * MT * D_MODEL);
    float4 vv = in[i];
    __nv_bfloat16 h0 = __float2bfloat16(vv.x), h1 = __float2bfloat16(vv.y);
    __nv_bfloat16 h2 = __float2bfloat16(vv.z), h3 = __float2bfloat16(vv.w);
    hi[2 * i]     = __halves2bfloat162(h0, h1);
    hi[2 * i + 1] = __halves2bfloat162(h2, h3);
    lo[2 * i]     = __halves2bfloat162(__float2bfloat16(vv.x - __bfloat162float(h0)),
                                       __float2bfloat16(vv.y - __bfloat162float(h1)));
    lo[2 * i + 1] = __halves2bfloat162(__float2bfloat16(vv.z - __bfloat162float(h2)),
                                       __float2bfloat16(vv.w - __bfloat162float(h3)));
}

__global__ void wt_split_b_kernel(const float* __restrict__ W0,
                                  const float* __restrict__ W1,
                                  const float* __restrict__ W2,
                                  const float* __restrict__ W3,
                                  __nv_bfloat16* __restrict__ Wth,
                                  __nv_bfloat16* __restrict__ Wtl) {
    __shared__ float ts[32][33];
    int z = blockIdx.z;
    const float* W = (z == 0) ? W0 : (z == 1) ? W1 : (z == 2) ? W2 : W3;
    __nv_bfloat16* oh = Wth + (size_t)z * D_MODEL * D_MODEL;
    __nv_bfloat16* ol = Wtl + (size_t)z * D_MODEL * D_MODEL;
    int n0 = blockIdx.x * 32, k0 = blockIdx.y * 32;
    ts[threadIdx.y][threadIdx.x] = W[(size_t)(k0 + threadIdx.y) * 512 + n0 + threadIdx.x];
    __syncthreads();
    int n = n0 + threadIdx.y, k = k0 + threadIdx.x;
    float v = ts[threadIdx.x][threadIdx.y];
    __nv_bfloat16 hv = __float2bfloat16(v);
    oh[(size_t)n * 512 + k] = hv;
    ol[(size_t)n * 512 + k] = __float2bfloat16(v - __bfloat162float(hv));
}

// ============================================================================
// HMMA GEMM (cp.async double-buffered): C[8192x512] = A @ Wt^T + bias, bf16x3.
// CTA 128x128, BK=32, 8 warps (4x2), warp tile 32x64.
// z: 0=Q, 1=K (bf16 hi/lo head-split), 2=V (f32 head-split), 3=out proj (f32).
// ============================================================================
#define GRB    80      // smem row bytes (40 bf16)
#define GTILE  10240   // 128 rows
#define GSTAGE 40960   // 4 tiles
#define G_SMEM (2 * GSTAGE)

__global__ __launch_bounds__(256) void mm_gemm(
    const __nv_bfloat16* __restrict__ Ahb, const __nv_bfloat16* __restrict__ Alb,
    const __nv_bfloat16* __restrict__ Wthb, const __nv_bfloat16* __restrict__ Wtlb,
    const float* __restrict__ bq, const float* __restrict__ bk,
    const float* __restrict__ bv, const float* __restrict__ bo,
    __nv_bfloat16* __restrict__ Qh, __nv_bfloat16* __restrict__ Ql,
    __nv_bfloat16* __restrict__ Kh, __nv_bfloat16* __restrict__ Kl,
    float* __restrict__ Vf, float* __restrict__ dout, int zofs) {
    extern __shared__ __align__(16) char smg[];
    const int tid = threadIdx.x, wid = tid >> 5, lane = tid & 31;
    const int wm = wid >> 1, wn = wid & 1;
    const int gr = lane >> 2, gc = lane & 3;
    const int m0 = blockIdx.y * 128, n0 = blockIdx.x * 128;
    const int z = blockIdx.z + zofs;

    const __nv_bfloat16* Ah = Ahb + (size_t)((z == 3) ? 0 : z) * MT * D_MODEL;
    const __nv_bfloat16* Al = Alb + (size_t)((z == 3) ? 0 : z) * MT * D_MODEL;
    const __nv_bfloat16* Bh = Wthb + (size_t)z * D_MODEL * D_MODEL;
    const __nv_bfloat16* Bl = Wtlb + (size_t)z * D_MODEL * D_MODEL;
    const float* bias = (z == 0) ? bq : (z == 1) ? bk : (z == 2) ? bv : bo;

    const uint32_t sb = smem_to_u32(smg);
    const uint32_t rAh = (uint32_t)(wm * 32 + (lane & 15)) * GRB + (((lane >> 4) & 1) << 4);
    const uint32_t rBh = 2u * GTILE +
        (uint32_t)(wn * 64 + (lane & 7) + (((lane >> 4) & 1) << 3)) * GRB +
        (((lane >> 3) & 1) << 4);

    const int pr = tid >> 2, pj = tid & 3;
    const uint32_t poff = (uint32_t)pr * GRB + pj * 16;

    float c[2][8][4];
#pragma unroll
    for (int i = 0; i < 2; i++)
#pragma unroll
        for (int j = 0; j < 8; j++)
#pragma unroll
            for (int e = 0; e < 4; e++) c[i][j][e] = 0.0f;

    {
#pragma unroll
        for (int t = 0; t < 2; t++) {
            int r = pr + t * 64;
            uint32_t d = sb + poff + (uint32_t)t * 64 * GRB;
            size_t ga = (size_t)(m0 + r) * 512 + pj * 8;
            size_t gb = (size_t)(n0 + r) * 512 + pj * 8;
            CP16(d, Ah + ga);
            CP16(d + GTILE, Al + ga);
            CP16(d + 2 * GTILE, Bh + gb);
            CP16(d + 3 * GTILE, Bl + gb);
        }
        CP_COMMIT();
    }

    for (int kc = 0; kc < 16; kc++) {
        const uint32_t stg = sb + (uint32_t)(kc & 1) * GSTAGE;
        CP_WAIT0();
        __syncthreads();
        if (kc < 15) {
            const int k0 = (kc + 1) * 32;
            const uint32_t nstg = sb + (uint32_t)((kc + 1) & 1) * GSTAGE;
#pragma unroll
            for (int t = 0; t < 2; t++) {
                int r = pr + t * 64;
                uint32_t d = nstg + poff + (uint32_t)t * 64 * GRB;
                size_t ga = (size_t)(m0 + r) * 512 + k0 + pj * 8;
                size_t gb = (size_t)(n0 + r) * 512 + k0 + pj * 8;
                CP16(d, Ah + ga);
                CP16(d + GTILE, Al + ga);
                CP16(d + 2 * GTILE, Bh + gb);
                CP16(d + 3 * GTILE, Bl + gb);
            }
            CP_COMMIT();
        }

        const uint32_t aAh = stg + rAh, aBh = stg + rBh;
#pragma unroll
        for (int ks = 0; ks < 2; ks++) {
            uint32_t ah[2][4], al[2][4];
            ldsm4(ah[0], aAh + ks * 32);
            ldsm4(ah[1], aAh + 16 * GRB + ks * 32);
            ldsm4(al[0], aAh + GTILE + ks * 32);
            ldsm4(al[1], aAh + GTILE + 16 * GRB + ks * 32);
#pragma unroll
            for (int nt2 = 0; nt2 < 4; nt2++) {
                uint32_t bh[4], bl[4];
                ldsm4(bh, aBh + nt2 * 16 * GRB + ks * 32);
                ldsm4(bl, aBh + GTILE + nt2 * 16 * GRB + ks * 32);
#pragma unroll
                for (int q = 0; q < 2; q++) {
                    int nt = nt2 * 2 + q;
#pragma unroll
                    for (int mt = 0; mt < 2; mt++) {
                        mma16816(c[mt][nt], ah[mt], &bh[q * 2]);
                        mma16816(c[mt][nt], al[mt], &bh[q * 2]);
                        mma16816(c[mt][nt], ah[mt], &bl[q * 2]);
                    }
                }
            }
        }
    }

    // Epilogue
#pragma unroll
    for (int mt = 0; mt < 2; mt++) {
#pragma unroll
        for (int half = 0; half < 2; half++) {
            int m = m0 + wm * 32 + mt * 16 + gr + half * 8;
            int bb = m >> 11, l = m & 2047;
#pragma unroll
            for (int nt = 0; nt < 8; nt++) {
                int n = n0 + wn * 64 + nt * 8 + 2 * gc;
                float v0 = c[mt][nt][half * 2 + 0] + bias[n];
                float v1 = c[mt][nt][half * 2 + 1] + bias[n + 1];
                if (z == 3) {
                    *(float2*)(dout + (size_t)m * 512 + n) = make_float2(v0, v1);
                } else if (z == 2) {
                    int h = n >> 6, d = n & 63;
                    *(float2*)(Vf + ((size_t)(bb * 8 + h) * SEQ + l) * DK + d) =
                        make_float2(v0, v1);
                } else {
                    int h = n >> 6, d = n & 63;
                    size_t o = ((size_t)(bb * 8 + h) * SEQ + l) * DK + d;
                    __nv_bfloat16 h0 = __float2bfloat16(v0);
                    __nv_bfloat16 h1 = __float2bfloat16(v1);
                    __nv_bfloat16* oh = (z == 0) ? Qh : Kh;
                    __nv_bfloat16* ol = (z == 0) ? Ql : Kl;
                    *(__nv_bfloat162*)(oh + o) = __halves2bfloat162(h0, h1);
                    *(__nv_bfloat162*)(ol + o) = __halves2bfloat162(
                        __float2bfloat16(v0 - __bfloat162float(h0)),
                        __float2bfloat16(v1 - __bfloat162float(h1)));
                }
            }
        }
    }
}

// ============================================================================
// HMMA flash attention over COMPACTED KV (niter = ceil(nk/64) ~ 17 tiles).
// CTA = 128 q rows x one (b,h); 8 warps x 16 q-rows.
// cp.async double-buffered; Q fragments in registers; no in-loop mask loads —
// only an index-vs-nk compare (bites in the final partial tile).
// Epilogue writes bf16 hi/lo split directly (input of output projection).
// ============================================================================
#define ARB   144                 // smem row bytes (72 bf16)
#define ATILE (256 * ARB)         // one stage: KH(64) KL(64) VH(64) VL(64) rows
#define A_SMEM (2 * ATILE)

__global__ __launch_bounds__(256) void mm_attn(
    const __nv_bfloat16* __restrict__ Qh, const __nv_bfloat16* __restrict__ Ql,
    const __nv_bfloat16* __restrict__ Kh, const __nv_bfloat16* __restrict__ Kl,
    const __nv_bfloat16* __restrict__ Vh, const __nv_bfloat16* __restrict__ Vl,
    const int* __restrict__ nkp,
    __nv_bfloat16* __restrict__ OutH, __nv_bfloat16* __restrict__ OutL) {
    extern __shared__ __align__(16) char smA[];

    const int tid = threadIdx.x, wid = tid >> 5, lane = tid & 31;
    const int gr = lane >> 2, gc = lane & 3;
    const int q0 = blockIdx.x * 128;
    const int bh = blockIdx.y, b = bh >> 3, h = bh & 7;
    const int nk = nkp[b];
    const int niter = (nk + 63) >> 6;

    const __nv_bfloat16* Qhp = Qh + (size_t)bh * SEQ * DK;
    const __nv_bfloat16* Qlp = Ql + (size_t)bh * SEQ * DK;
    const __nv_bfloat16* Khp = Kh + (size_t)bh * SEQ * DK;
    const __nv_bfloat16* Klp = Kl + (size_t)bh * SEQ * DK;
    const __nv_bfloat16* Vhp = Vh + (size_t)bh * DK * SEQ;
    const __nv_bfloat16* Vlp = Vl + (size_t)bh * DK * SEQ;

    const uint32_t sb = smem_to_u32(smA);
    const int pr = tid >> 3, pj = tid & 7;

    // ---- prefetch KV tile 0 into stage 0
    if (niter > 0) {
#pragma unroll
        for (int t = 0; t < 2; t++) {
            int r = pr + t * 32;
            uint32_t d = sb + (uint32_t)r * ARB + pj * 16;
            size_t gk = (size_t)r * DK + pj * 8;
            size_t gv = (size_t)r * SEQ + pj * 8;
            CP16(d, Khp + gk);
            CP16(d + 64 * ARB, Klp + gk);
            CP16(d + 128 * ARB, Vhp + gv);
            CP16(d + 192 * ARB, Vlp + gv);
        }
        CP_COMMIT();
    }

    // ---- stage Q into buffer 1, load fragments, recycle buffer
#pragma unroll
    for (int t = 0; t < 4; t++) {
        int i = tid + t * 256;
        int r = i >> 3, j = i & 7;
        char* dsth = smA + ATILE + (size_t)r * ARB + j * 16;
        char* dstl = smA + ATILE + (size_t)(128 + r) * ARB + j * 16;
        *(uint4*)dsth = *(const uint4*)(Qhp + (size_t)(q0 + r) * DK + j * 8);
        *(uint4*)dstl = *(const uint4*)(Qlp + (size_t)(q0 + r) * DK + j * 8);
    }
    __syncthreads();

    uint32_t qh[4][4], ql[4][4];
    {
        const uint32_t aQ = sb + ATILE +
            (uint32_t)(wid * 16 + (lane & 15)) * ARB + (((lane >> 4) & 1) << 4);
#pragma unroll
        for (int ks = 0; ks < 4; ks++) {
            ldsm4(qh[ks], aQ + ks * 32);
            ldsm4(ql[ks], aQ + 128 * ARB + ks * 32);
        }
    }
    CP_WAIT0();
    __syncthreads();  // Q frags read everywhere; stage 0 visible; buffer 1 free

    const uint32_t bro = (uint32_t)((lane & 7) + (((lane >> 4) & 1) << 3)) * ARB +
                         (((lane >> 3) & 1) << 4);

    const float L2E = 1.4426950408889634f;
    float m0_ = -1e30f, m1_ = -1e30f, l0_ = 0.0f, l1_ = 0.0f;
    float o[8][4];
#pragma unroll
    for (int j = 0; j < 8; j++)
#pragma unroll
        for (int e = 0; e < 4; e++) o[j][e] = 0.0f;

    for (int it = 0; it < niter; it++) {
        const int cur = it & 1;
        const uint32_t stg = sb + (uint32_t)cur * ATILE;
        const int kt = it * 64;

        if (it > 0) {
            CP_WAIT0();
            __syncthreads();
        }
        if (it + 1 < niter) {
            const int ktn = kt + 64;
            const uint32_t nstg = sb + (uint32_t)(1 - cur) * ATILE;
#pragma unroll
            for (int t = 0; t < 2; t++) {
                int r = pr + t * 32;
                uint32_t d = nstg + (uint32_t)r * ARB + pj * 16;
                size_t gk = (size_t)(ktn + r) * DK + pj * 8;
                size_t gv = (size_t)r * SEQ + ktn + pj * 8;
                CP16(d, Khp + gk);
                CP16(d + 64 * ARB, Klp + gk);
                CP16(d + 128 * ARB, Vhp + gv);
                CP16(d + 192 * ARB, Vlp + gv);
            }
            CP_COMMIT();
        }

        // ---- S = Q @ K^T (bf16x3)
        float s[8][4];
#pragma unroll
        for (int j = 0; j < 8; j++)
#pragma unroll
            for (int e = 0; e < 4; e++) s[j][e] = 0.0f;
        const uint32_t aKh = stg + bro, aKl = stg + 64 * ARB + bro;
#pragma unroll
        for (int ks = 0; ks < 4; ks++) {
#pragma unroll
            for (int nt2 = 0; nt2 < 4; nt2++) {
                uint32_t kh[4], kl[4];
                ldsm4(kh, aKh + nt2 * 16 * ARB + ks * 32);
                ldsm4(kl, aKl + nt2 * 16 * ARB + ks * 32);
#pragma unroll
                for (int q = 0; q < 2; q++) {
                    int nt = nt2 * 2 + q;
                    mma16816(s[nt], qh[ks], &kh[q * 2]);
                    mma16816(s[nt], ql[ks], &kh[q * 2]);
                    mma16816(s[nt], qh[ks], &kl[q * 2]);
                }
            }
        }

        // ---- validity (col < nk) + scale + row max
        float mx0 = -3.0e38f, mx1 = -3.0e38f;
        float mk[8][2];
#pragma unroll
        for (int nt = 0; nt < 8; nt++) {
            int cb = kt + nt * 8 + 2 * gc;
            bool v0 = cb < nk, v1 = (cb + 1) < nk;
            mk[nt][0] = v0 ? 1.0f : 0.0f;
            mk[nt][1] = v1 ? 1.0f : 0.0f;
            s[nt][0] = v0 ? s[nt][0] * 0.125f : -3.0e38f;
            s[nt][1] = v1 ? s[nt][1] * 0.125f : -3.0e38f;
            s[nt][2] = v0 ? s[nt][2] * 0.125f : -3.0e38f;
            s[nt][3] = v1 ? s[nt][3] * 0.125f : -3.0e38f;
            mx0 = fmaxf(mx0, fmaxf(s[nt][0], s[nt][1]));
            mx1 = fmaxf(mx1, fmaxf(s[nt][2], s[nt][3]));
        }
        mx0 = fmaxf(mx0, __shfl_xor_sync(0xffffffffu, mx0, 1));
        mx0 = fmaxf(mx0, __shfl_xor_sync(0xffffffffu, mx0, 2));
        mx1 = fmaxf(mx1, __shfl_xor_sync(0xffffffffu, mx1, 1));
        mx1 = fmaxf(mx1, __shfl_xor_sync(0xffffffffu, mx1, 2));
        float mn0 = fmaxf(m0_, mx0), mn1 = fmaxf(m1_, mx1);
        float al0 = fexp2((m0_ - mn0) * L2E), al1 = fexp2((m1_ - mn1) * L2E);
        m0_ = mn0;
        m1_ = mn1;

        // ---- exp, sums, pack P into mma A-fragments (hi/lo)
        uint32_t pa_h[4][4], pa_l[4][4];
        float sm0 = 0.0f, sm1 = 0.0f;
#pragma unroll
        for (int nt = 0; nt < 8; nt++) {
            float p0 = fexp2((s[nt][0] - mn0) * L2E) * mk[nt][0];
            float p1 = fexp2((s[nt][1] - mn0) * L2E) * mk[nt][1];
            float p2 = fexp2((s[nt][2] - mn1) * L2E) * mk[nt][0];
            float p3 = fexp2((s[nt][3] - mn1) * L2E) * mk[nt][1];
            sm0 += p0 + p1;
            sm1 += p2 + p3;
            __nv_bfloat16 h0 = __float2bfloat16(p0), h1 = __float2bfloat16(p1);
            __nv_bfloat16 h2 = __float2bfloat16(p2), h3 = __float2bfloat16(p3);
            int kp = nt >> 1, q = nt & 1;
            pa_h[kp][q * 2 + 0] = packbf2(h0, h1);
            pa_h[kp][q * 2 + 1] = packbf2(h2, h3);
            pa_l[kp][q * 2 + 0] =
                packbf2(__float2bfloat16(p0 - __bfloat162float(h0)),
                        __float2bfloat16(p1 - __bfloat162float(h1)));
            pa_l[kp][q * 2 + 1] =
                packbf2(__float2bfloat16(p2 - __bfloat162float(h2)),
                        __float2bfloat16(p3 - __bfloat162float(h3)));
        }
        sm0 += __shfl_xor_sync(0xffffffffu, sm0, 1);
        sm0 += __shfl_xor_sync(0xffffffffu, sm0, 2);
        sm1 += __shfl_xor_sync(0xffffffffu, sm1, 1);
        sm1 += __shfl_xor_sync(0xffffffffu, sm1, 2);
        l0_ = l0_ * al0 + sm0;
        l1_ = l1_ * al1 + sm1;

#pragma unroll
        for (int j = 0; j < 8; j++) {
            o[j][0] *= al0;
            o[j][1] *= al0;
            o[j][2] *= al1;
            o[j][3] *= al1;
        }

        // ---- O += P @ V (bf16x3)
        const uint32_t aVh = stg + 128 * ARB + bro, aVl = stg + 192 * ARB + bro;
#pragma unroll
        for (int kp = 0; kp < 4; kp++) {
#pragma unroll
            for (int nt2 = 0; nt2 < 4; nt2++) {
                uint32_t vh[4], vl[4];
                ldsm4(vh, aVh + nt2 * 16 * ARB + kp * 32);
                ldsm4(vl, aVl + nt2 * 16 * ARB + kp * 32);
#pragma unroll
                for (int q = 0; q < 2; q++) {
                    int nt = nt2 * 2 + q;
                    mma16816(o[nt], pa_h[kp], &vh[q * 2]);
                    mma16816(o[nt], pa_l[kp], &vh[q * 2]);
                    mma16816(o[nt], pa_h[kp], &vl[q * 2]);
                }
            }
        }
    }

    // ---- normalize (guard all-masked) + store bf16 hi/lo split (B, L, H*64)
    float inv0 = (l0_ > 0.0f) ? 1.0f / l0_ : 0.0f;
    float inv1 = (l1_ > 0.0f) ? 1.0f / l1_ : 0.0f;
    int r0 = q0 + wid * 16 + gr, r1 = r0 + 8;
    size_t base0 = (size_t)(b * SEQ + r0) * D_MODEL + h * DK;
    size_t base1 = (size_t)(b * SEQ + r1) * D_MODEL + h * DK;
#pragma unroll
    for (int nt = 0; nt < 8; nt++) {
        int cl = nt * 8 + 2 * gc;
        float v0 = o[nt][0] * inv0, v1 = o[nt][1] * inv0;
        float v2 = o[nt][2] * inv1, v3 = o[nt][3] * inv1;
        __nv_bfloat16 h0 = __float2bfloat16(v0), h1 = __float2bfloat16(v1);
        __nv_bfloat16 h2 = __float2bfloat16(v2), h3 = __float2bfloat16(v3);
        *(__nv_bfloat162*)(OutH + base0 + cl) = __halves2bfloat162(h0, h1);
        *(__nv_bfloat162*)(OutL + base0 + cl) = __halves2bfloat162(
            __float2bfloat16(v0 - __bfloat162float(h0)),
            __float2bfloat16(v1 - __bfloat162float(h1)));
        *(__nv_bfloat162*)(OutH + base1 + cl) = __halves2bfloat162(h2, h3);
        *(__nv_bfloat162*)(OutL + base1 + cl) = __halves2bfloat162(
            __float2bfloat16(v2 - __bfloat162float(h2)),
            __float2bfloat16(v3 - __bfloat162float(h3)));
    }
}

// ============================================================================
// Launch: 7 kernels total
// ============================================================================
extern "C" void kernel_launch(void* const* d_in, const int* in_sizes, int n_in,
                              void* d_out, int out_size) {
    const float* query = (const float*)d_in[0];
    const float* key   = (const float*)d_in[1];
    const float* value = (const float*)d_in[2];
    const int*   mask  = (const int*)d_in[3];
    const float* Wq = (const float*)d_in[4];
    const float* bq = (const float*)d_in[5];
    const float* Wk = (const float*)d_in[6];
    const float* bk = (const float*)d_in[7];
    const float* Wv = (const float*)d_in[8];
    const float* bv = (const float*)d_in[9];
    const float* Wo = (const float*)d_in[10];
    const float* bo = (const float*)d_in[11];

    __nv_bfloat16 *Ah, *Al, *Wth, *Wtl, *Qh, *Ql, *Kh, *Kl, *Khc, *Klc, *Vth, *Vtl;
    float *Vf;
    int *idx, *nk;
    cudaGetSymbolAddress((void**)&Ah, g_Ah);
    cudaGetSymbolAddress((void**)&Al, g_Al);
    cudaGetSymbolAddress((void**)&Wth, g_Wth);
    cudaGetSymbolAddress((void**)&Wtl, g_Wtl);
    cudaGetSymbolAddress((void**)&Qh, g_Qh);
    cudaGetSymbolAddress((void**)&Ql, g_Ql);
    cudaGetSymbolAddress((void**)&Kh, g_Kh);
    cudaGetSymbolAddress((void**)&Kl, g_Kl);
    cudaGetSymbolAddress((void**)&Khc, g_Khc);
    cudaGetSymbolAddress((void**)&Klc, g_Klc);
    cudaGetSymbolAddress((void**)&Vf, g_Vf);
    cudaGetSymbolAddress((void**)&Vth, g_Vth);
    cudaGetSymbolAddress((void**)&Vtl, g_Vtl);
    cudaGetSymbolAddress((void**)&idx, g_idx);
    cudaGetSymbolAddress((void**)&nk, g_nk);

    cudaFuncSetAttribute(mm_gemm, cudaFuncAttributeMaxDynamicSharedMemorySize,
                         G_SMEM);
    cudaFuncSetAttribute(mm_attn, cudaFuncAttributeMaxDynamicSharedMemorySize,
                         A_SMEM);

    const int N4 = MT * D_MODEL / 4;

    // 1. mask scan (overlappable with everything up to the gather)
    mask_scan_kernel<<<BATCH, 1024>>>(mask, idx, nk);
    // 2. all 4 weight transposes/splits
    wt_split_b_kernel<<<dim3(16, 16, 4), dim3(32, 32)>>>(Wq, Wk, Wv, Wo, Wth, Wtl);
    // 3. query/key/value input splits
    split_b_kernel<<<dim3(N4 / 256, 3), 256>>>((const float4*)query,
                                               (const float4*)key,
                                               (const float4*)value, Ah, Al, N4);
    // 4. Q/K/V projections (one launch, z-batched)
    mm_gemm<<<dim3(4, 64, 3), 256, G_SMEM>>>(Ah, Al, Wth, Wtl, bq, bk, bv, bo,
                                             Qh, Ql, Kh, Kl, Vf, nullptr, 0);
    // 5. KV compaction (K gather + V gather/transpose/split)
    kv_gather_kernel<<<dim3(SEQ / 64, BH), 256>>>(Kh, Kl, Vf, idx, nk,
                                                  Khc, Klc, Vth, Vtl);
    // 6. attention over compacted KV (writes hi/lo split into Ah/Al slot 0)
    mm_attn<<<dim3(SEQ / 128, BH), 256, A_SMEM>>>(Qh, Ql, Khc, Klc, Vth, Vtl,
                                                  nk, Ah, Al);
    // 7. output projection
    mm_gemm<<<dim3(4, 64, 1), 256, G_SMEM>>>(Ah, Al, Wth, Wtl, bq, bk, bv, bo,
                                             nullptr, nullptr, nullptr, nullptr,
                                             nullptr, (float*)d_out, 3);
}

// round 10
// speedup vs baseline: 3.9705x; 1.1805x over previous
#include <cuda_runtime.h>
#include <cuda_bf16.h>
#include <cstdint>

#define NUM_HEADS 8
#define D_MODEL   512
#define DK        64
#define SEQ       2048
#define BATCH     4
#define MT        (BATCH * SEQ)        // 8192
#define BH        (BATCH * NUM_HEADS)  // 32

// ============================================================================
// Scratch (device globals — no allocation allowed)
// ============================================================================
__device__ __align__(16) __nv_bfloat16 g_Ah[3 * MT * D_MODEL];
__device__ __align__(16) __nv_bfloat16 g_Al[3 * MT * D_MODEL];
__device__ __align__(16) __nv_bfloat16 g_Wth[4 * D_MODEL * D_MODEL];
__device__ __align__(16) __nv_bfloat16 g_Wtl[4 * D_MODEL * D_MODEL];
__device__ __align__(16) __nv_bfloat16 g_Qh[BH * SEQ * DK];
__device__ __align__(16) __nv_bfloat16 g_Ql[BH * SEQ * DK];
__device__ __align__(16) __nv_bfloat16 g_Kh[BH * SEQ * DK];
__device__ __align__(16) __nv_bfloat16 g_Kl[BH * SEQ * DK];
__device__ __align__(16) __nv_bfloat16 g_Khc[BH * SEQ * DK];  // compacted K hi
__device__ __align__(16) __nv_bfloat16 g_Klc[BH * SEQ * DK];  // compacted K lo
__device__ __align__(16) float         g_Vf[BH * SEQ * DK];
__device__ __align__(16) __nv_bfloat16 g_Vth[BH * DK * SEQ];  // compacted V^T hi
__device__ __align__(16) __nv_bfloat16 g_Vtl[BH * DK * SEQ];  // compacted V^T lo
__device__ int g_idx[BATCH * SEQ];
__device__ int g_nk[BATCH];

// 0.125 (1/sqrt(d_k)) * log2(e): folded into Q projection so S is in log2 units
#define QSCALE 0.18033688011117128f

// ============================================================================
// PTX primitives (all legal at compute_103 baseline)
// ============================================================================
__device__ __forceinline__ uint32_t smem_to_u32(const void* p) {
    uint32_t a;
    asm("{ .reg .u64 t; cvta.to.shared.u64 t, %1; cvt.u32.u64 %0, t; }"
        : "=r"(a) : "l"(p));
    return a;
}

__device__ __forceinline__ void ldsm4(uint32_t* r, uint32_t addr) {
    asm volatile("ldmatrix.sync.aligned.m8n8.x4.shared.b16 {%0,%1,%2,%3}, [%4];"
                 : "=r"(r[0]), "=r"(r[1]), "=r"(r[2]), "=r"(r[3]) : "r"(addr));
}

__device__ __forceinline__ void mma16816(float* c, const uint32_t* a,
                                         const uint32_t* b) {
    asm volatile(
        "mma.sync.aligned.m16n8k16.row.col.f32.bf16.bf16.f32 "
        "{%0,%1,%2,%3}, {%4,%5,%6,%7}, {%8,%9}, {%0,%1,%2,%3};"
        : "+f"(c[0]), "+f"(c[1]), "+f"(c[2]), "+f"(c[3])
        : "r"(a[0]), "r"(a[1]), "r"(a[2]), "r"(a[3]), "r"(b[0]), "r"(b[1]));
}

#define CP16(dst, src) \
    asm volatile("cp.async.cg.shared.global [%0], [%1], 16;" \
                 :: "r"(dst), "l"(src) : "memory")
#define CP_COMMIT() asm volatile("cp.async.commit_group;" ::: "memory")
#define CP_WAIT0()  asm volatile("cp.async.wait_group 0;" ::: "memory")

// exp2 via magic-constant round + degree-4 poly on [-0.5, 0.5]; t <= 0.
// Clamp makes padded/init lanes yield ~1.2e-38 (negligible in all sums).
__device__ __forceinline__ float fexp2m(float t) {
    t = fmaxf(t, -126.0f);
    float z = t + 12582912.0f;               // round-to-nearest int in mantissa
    float f = t - (z - 12582912.0f);         // f in [-0.5, 0.5]
    float p = fmaf(f, 0.0096181291f, 0.0555041087f);
    p = fmaf(p, f, 0.2402265069f);
    p = fmaf(p, f, 0.6931471806f);
    p = fmaf(p, f, 1.0f);
    uint32_t sb = (uint32_t)((__float_as_int(z) + 127) << 23);
    return __int_as_float(sb) * p;
}

// ============================================================================
// Mask prefix scan: per batch, build compacted index list + count
// ============================================================================
__global__ __launch_bounds__(1024) void mask_scan_kernel(
    const int* __restrict__ mask, int* __restrict__ idx, int* __restrict__ nk) {
    const int b = blockIdx.x, tid = threadIdx.x;
    const int lane = tid & 31, w = tid >> 5;
    const int* mp = mask + b * SEQ;
    int e0 = (mp[2 * tid] != 0), e1 = (mp[2 * tid + 1] != 0);
    int tsum = e0 + e1;
    int v = tsum;
#pragma unroll
    for (int o = 1; o < 32; o <<= 1) {
        int u = __shfl_up_sync(0xffffffffu, v, o);
        if (lane >= o) v += u;
    }
    __shared__ int ws[32];
    if (lane == 31) ws[w] = v;
    __syncthreads();
    if (w == 0) {
        int x = ws[lane];
#pragma unroll
        for (int o = 1; o < 32; o <<= 1) {
            int u = __shfl_up_sync(0xffffffffu, x, o);
            if (lane >= o) x += u;
        }
        ws[lane] = x;
    }
    __syncthreads();
    int base = ((w > 0) ? ws[w - 1] : 0) + (v - tsum);
    if (e0) idx[b * SEQ + base] = 2 * tid;
    if (e1) idx[b * SEQ + base + e0] = 2 * tid + 1;
    if (tid == 0) nk[b] = ws[31];
}

// ============================================================================
// KV gather: pack unmasked K rows (hi/lo) densely; gather+transpose+split V.
// ============================================================================
__global__ __launch_bounds__(256) void kv_gather_kernel(
    const __nv_bfloat16* __restrict__ Kh, const __nv_bfloat16* __restrict__ Kl,
    const float* __restrict__ Vf, const int* __restrict__ idx,
    const int* __restrict__ nk,
    __nv_bfloat16* __restrict__ Khc, __nv_bfloat16* __restrict__ Klc,
    __nv_bfloat16* __restrict__ Vth, __nv_bfloat16* __restrict__ Vtl) {
    const int t = blockIdx.x, bh = blockIdx.y, b = bh >> 3;
    const int tid = threadIdx.x;
    const int n = nk[b];
    const int j0 = t * 64;
    if (j0 >= ((n + 63) & ~63)) return;
    const int* idxb = idx + b * SEQ;

    const uint4 z4 = make_uint4(0, 0, 0, 0);
#pragma unroll
    for (int t2 = 0; t2 < 2; t2++) {
        int i = tid + t2 * 256;
        int r = i >> 3, j = i & 7;
        int jj = j0 + r;
        int row = (jj < n) ? idxb[jj] : -1;
        size_t src = ((size_t)bh * SEQ + row) * DK + j * 8;
        size_t dst = ((size_t)bh * SEQ + jj) * DK + j * 8;
        *(uint4*)(Khc + dst) = (row >= 0) ? *(const uint4*)(Kh + src) : z4;
        *(uint4*)(Klc + dst) = (row >= 0) ? *(const uint4*)(Kl + src) : z4;
    }

    __shared__ float ts[64][65];
    for (int i = tid; i < 4096; i += 256) {
        int r = i >> 6, c = i & 63;
        int jj = j0 + r;
        int row = (jj < n) ? idxb[jj] : -1;
        ts[r][c] = (row >= 0) ? Vf[((size_t)bh * SEQ + row) * DK + c] : 0.0f;
    }
    __syncthreads();
    for (int i = tid; i < 4096; i += 256) {
        int d = i >> 6, c = i & 63;
        float v = ts[c][d];
        __nv_bfloat16 hv = __float2bfloat16(v);
        size_t o = ((size_t)bh * DK + d) * SEQ + j0 + c;
        Vth[o] = hv;
        Vtl[o] = __float2bfloat16(v - __bfloat162float(hv));
    }
}

// ============================================================================
// Prep kernels (batched over z)
// ============================================================================
__global__ void split_b_kernel(const float4* __restrict__ q,
                               const float4* __restrict__ k,
                               const float4* __restrict__ v,
                               __nv_bfloat16* __restrict__ Ah,
                               __nv_bfloat16* __restrict__ Al, int n4) {
    int i = blockIdx.x * blockDim.x + threadIdx.x;
    if (i >= n4) return;
    int z = blockIdx.y;
    const float4* in = (z == 0) ? q : (z == 1) ? k : v;
    __nv_bfloat162* hi = (__nv_bfloat162*)(Ah + (size_t)z * MT * D_MODEL);
    __nv_bfloat162* lo = (__nv_bfloat162*)(Al + (size_t)z * MT * D_MODEL);
    float4 vv = in[i];
    __nv_bfloat16 h0 = __float2bfloat16(vv.x), h1 = __float2bfloat16(vv.y);
    __nv_bfloat16 h2 = __float2bfloat16(vv.z), h3 = __float2bfloat16(vv.w);
    hi[2 * i]     = __halves2bfloat162(h0, h1);
    hi[2 * i + 1] = __halves2bfloat162(h2, h3);
    lo[2 * i]     = __halves2bfloat162(__float2bfloat16(vv.x - __bfloat162float(h0)),
                                       __float2bfloat16(vv.y - __bfloat162float(h1)));
    lo[2 * i + 1] = __halves2bfloat162(__float2bfloat16(vv.z - __bfloat162float(h2)),
                                       __float2bfloat16(vv.w - __bfloat162float(h3)));
}

__global__ void wt_split_b_kernel(const float* __restrict__ W0,
                                  const float* __restrict__ W1,
                                  const float* __restrict__ W2,
                                  const float* __restrict__ W3,
                                  __nv_bfloat16* __restrict__ Wth,
                                  __nv_bfloat16* __restrict__ Wtl) {
    __shared__ float ts[32][33];
    int z = blockIdx.z;
    const float* W = (z == 0) ? W0 : (z == 1) ? W1 : (z == 2) ? W2 : W3;
    __nv_bfloat16* oh = Wth + (size_t)z * D_MODEL * D_MODEL;
    __nv_bfloat16* ol = Wtl + (size_t)z * D_MODEL * D_MODEL;
    int n0 = blockIdx.x * 32, k0 = blockIdx.y * 32;
    ts[threadIdx.y][threadIdx.x] = W[(size_t)(k0 + threadIdx.y) * 512 + n0 + threadIdx.x];
    __syncthreads();
    int n = n0 + threadIdx.y, k = k0 + threadIdx.x;
    float v = ts[threadIdx.x][threadIdx.y];
    __nv_bfloat16 hv = __float2bfloat16(v);
    oh[(size_t)n * 512 + k] = hv;
    ol[(size_t)n * 512 + k] = __float2bfloat16(v - __bfloat162float(hv));
}

// ============================================================================
// HMMA GEMM (cp.async double-buffered), pass-reordered mainloop:
// all mmas within a pass hit distinct accumulators (RAW distance 16).
// z: 0=Q (bf16 hi/lo head-split, pre-scaled by QSCALE), 1=K (hi/lo head-split),
// 2=V (f32 head-split), 3=out proj (f32 row-major to d_out).
// ============================================================================
#define GRB    80      // smem row bytes (40 bf16)
#define GTILE  10240   // 128 rows
#define GSTAGE 40960   // 4 tiles
#define G_SMEM (2 * GSTAGE)

__global__ __launch_bounds__(256, 2) void mm_gemm(
    const __nv_bfloat16* __restrict__ Ahb, const __nv_bfloat16* __restrict__ Alb,
    const __nv_bfloat16* __restrict__ Wthb, const __nv_bfloat16* __restrict__ Wtlb,
    const float* __restrict__ bq, const float* __restrict__ bk,
    const float* __restrict__ bv, const float* __restrict__ bo,
    __nv_bfloat16* __restrict__ Qh, __nv_bfloat16* __restrict__ Ql,
    __nv_bfloat16* __restrict__ Kh, __nv_bfloat16* __restrict__ Kl,
    float* __restrict__ Vf, float* __restrict__ dout, int zofs) {
    extern __shared__ __align__(16) char smg[];
    const int tid = threadIdx.x, wid = tid >> 5, lane = tid & 31;
    const int wm = wid >> 1, wn = wid & 1;
    const int gr = lane >> 2, gc = lane & 3;
    const int m0 = blockIdx.y * 128, n0 = blockIdx.x * 128;
    const int z = blockIdx.z + zofs;

    const __nv_bfloat16* Ah = Ahb + (size_t)((z == 3) ? 0 : z) * MT * D_MODEL;
    const __nv_bfloat16* Al = Alb + (size_t)((z == 3) ? 0 : z) * MT * D_MODEL;
    const __nv_bfloat16* Bh = Wthb + (size_t)z * D_MODEL * D_MODEL;
    const __nv_bfloat16* Bl = Wtlb + (size_t)z * D_MODEL * D_MODEL;
    const float* bias = (z == 0) ? bq : (z == 1) ? bk : (z == 2) ? bv : bo;

    const uint32_t sb = smem_to_u32(smg);
    const uint32_t rAh = (uint32_t)(wm * 32 + (lane & 15)) * GRB + (((lane >> 4) & 1) << 4);
    const uint32_t rBh = 2u * GTILE +
        (uint32_t)(wn * 64 + (lane & 7) + (((lane >> 4) & 1) << 3)) * GRB +
        (((lane >> 3) & 1) << 4);

    const int pr = tid >> 2, pj = tid & 3;
    const uint32_t poff = (uint32_t)pr * GRB + pj * 16;

    float c[2][8][4];
#pragma unroll
    for (int i = 0; i < 2; i++)
#pragma unroll
        for (int j = 0; j < 8; j++)
#pragma unroll
            for (int e = 0; e < 4; e++) c[i][j][e] = 0.0f;

    {
#pragma unroll
        for (int t = 0; t < 2; t++) {
            int r = pr + t * 64;
            uint32_t d = sb + poff + (uint32_t)t * 64 * GRB;
            size_t ga = (size_t)(m0 + r) * 512 + pj * 8;
            size_t gb = (size_t)(n0 + r) * 512 + pj * 8;
            CP16(d, Ah + ga);
            CP16(d + GTILE, Al + ga);
            CP16(d + 2 * GTILE, Bh + gb);
            CP16(d + 3 * GTILE, Bl + gb);
        }
        CP_COMMIT();
    }

    for (int kc = 0; kc < 16; kc++) {
        const uint32_t stg = sb + (uint32_t)(kc & 1) * GSTAGE;
        CP_WAIT0();
        __syncthreads();
        if (kc < 15) {
            const int k0 = (kc + 1) * 32;
            const uint32_t nstg = sb + (uint32_t)((kc + 1) & 1) * GSTAGE;
#pragma unroll
            for (int t = 0; t < 2; t++) {
                int r = pr + t * 64;
                uint32_t d = nstg + poff + (uint32_t)t * 64 * GRB;
                size_t ga = (size_t)(m0 + r) * 512 + k0 + pj * 8;
                size_t gb = (size_t)(n0 + r) * 512 + k0 + pj * 8;
                CP16(d, Ah + ga);
                CP16(d + GTILE, Al + ga);
                CP16(d + 2 * GTILE, Bh + gb);
                CP16(d + 3 * GTILE, Bl + gb);
            }
            CP_COMMIT();
        }

        const uint32_t aAh = stg + rAh, aBh = stg + rBh;
#pragma unroll
        for (int ks = 0; ks < 2; ks++) {
            uint32_t ah[2][4], al[2][4], bfr[4][4];
            ldsm4(ah[0], aAh + ks * 32);
            ldsm4(ah[1], aAh + 16 * GRB + ks * 32);
            ldsm4(al[0], aAh + GTILE + ks * 32);
            ldsm4(al[1], aAh + GTILE + 16 * GRB + ks * 32);
#pragma unroll
            for (int nt2 = 0; nt2 < 4; nt2++)
                ldsm4(bfr[nt2], aBh + nt2 * 16 * GRB + ks * 32);
            // pass 1: Ah*Bh — 16 independent mmas
#pragma unroll
            for (int nt2 = 0; nt2 < 4; nt2++)
#pragma unroll
                for (int q = 0; q < 2; q++)
#pragma unroll
                    for (int mt = 0; mt < 2; mt++)
                        mma16816(c[mt][nt2 * 2 + q], ah[mt], &bfr[nt2][q * 2]);
            // pass 2: Al*Bh
#pragma unroll
            for (int nt2 = 0; nt2 < 4; nt2++)
#pragma unroll
                for (int q = 0; q < 2; q++)
#pragma unroll
                    for (int mt = 0; mt < 2; mt++)
                        mma16816(c[mt][nt2 * 2 + q], al[mt], &bfr[nt2][q * 2]);
            // reload B = Bl, pass 3: Ah*Bl
#pragma unroll
            for (int nt2 = 0; nt2 < 4; nt2++)
                ldsm4(bfr[nt2], aBh + GTILE + nt2 * 16 * GRB + ks * 32);
#pragma unroll
            for (int nt2 = 0; nt2 < 4; nt2++)
#pragma unroll
                for (int q = 0; q < 2; q++)
#pragma unroll
                    for (int mt = 0; mt < 2; mt++)
                        mma16816(c[mt][nt2 * 2 + q], ah[mt], &bfr[nt2][q * 2]);
        }
    }

    // Epilogue
#pragma unroll
    for (int mt = 0; mt < 2; mt++) {
#pragma unroll
        for (int half = 0; half < 2; half++) {
            int m = m0 + wm * 32 + mt * 16 + gr + half * 8;
            int bb = m >> 11, l = m & 2047;
#pragma unroll
            for (int nt = 0; nt < 8; nt++) {
                int n = n0 + wn * 64 + nt * 8 + 2 * gc;
                float v0 = c[mt][nt][half * 2 + 0] + bias[n];
                float v1 = c[mt][nt][half * 2 + 1] + bias[n + 1];
                if (z == 3) {
                    *(float2*)(dout + (size_t)m * 512 + n) = make_float2(v0, v1);
                } else if (z == 2) {
                    int h = n >> 6, d = n & 63;
                    *(float2*)(Vf + ((size_t)(bb * 8 + h) * SEQ + l) * DK + d) =
                        make_float2(v0, v1);
                } else {
                    if (z == 0) { v0 *= QSCALE; v1 *= QSCALE; }
                    int h = n >> 6, d = n & 63;
                    size_t o = ((size_t)(bb * 8 + h) * SEQ + l) * DK + d;
                    __nv_bfloat16 h0 = __float2bfloat16(v0);
                    __nv_bfloat16 h1 = __float2bfloat16(v1);
                    __nv_bfloat16* oh = (z == 0) ? Qh : Kh;
                    __nv_bfloat16* ol = (z == 0) ? Ql : Kl;
                    *(__nv_bfloat162*)(oh + o) = __halves2bfloat162(h0, h1);
                    *(__nv_bfloat162*)(ol + o) = __halves2bfloat162(
                        __float2bfloat16(v0 - __bfloat162float(h0)),
                        __float2bfloat16(v1 - __bfloat162float(h1)));
                }
            }
        }
    }
}

// ============================================================================
// HMMA flash attention over compacted KV. 2 CTAs/SM (launch_bounds(256,2)):
// Q kept in smem (per-iter ldsm), pass-reordered QK/PV, log2-domain scores
// (QSCALE pre-folded), magic exp2, clamp-based masking (no mk multiplies).
// ============================================================================
#define ARB   144                 // smem row bytes (72 bf16)
#define ATILE (256 * ARB)         // one stage: KH(64) KL(64) VH(64) VL(64)
#define QOFF  (2 * ATILE)         // Q region: QH(128) QL(128)
#define A_SMEM (2 * ATILE + 256 * ARB)   // 110592 bytes

__global__ __launch_bounds__(256, 2) void mm_attn(
    const __nv_bfloat16* __restrict__ Qh, const __nv_bfloat16* __restrict__ Ql,
    const __nv_bfloat16* __restrict__ Kh, const __nv_bfloat16* __restrict__ Kl,
    const __nv_bfloat16* __restrict__ Vh, const __nv_bfloat16* __restrict__ Vl,
    const int* __restrict__ nkp,
    __nv_bfloat16* __restrict__ OutH, __nv_bfloat16* __restrict__ OutL) {
    extern __shared__ __align__(16) char smA[];

    const int tid = threadIdx.x, wid = tid >> 5, lane = tid & 31;
    const int gr = lane >> 2, gc = lane & 3;
    const int q0 = blockIdx.x * 128;
    const int bh = blockIdx.y, b = bh >> 3, h = bh & 7;
    const int nk = nkp[b];
    const int niter = (nk + 63) >> 6;

    const __nv_bfloat16* Qhp = Qh + (size_t)bh * SEQ * DK;
    const __nv_bfloat16* Qlp = Ql + (size_t)bh * SEQ * DK;
    const __nv_bfloat16* Khp = Kh + (size_t)bh * SEQ * DK;
    const __nv_bfloat16* Klp = Kl + (size_t)bh * SEQ * DK;
    const __nv_bfloat16* Vhp = Vh + (size_t)bh * DK * SEQ;
    const __nv_bfloat16* Vlp = Vl + (size_t)bh * DK * SEQ;

    const uint32_t sb = smem_to_u32(smA);
    const int pr = tid >> 3, pj = tid & 7;

    // ---- prefetch KV tile 0 into stage 0
    if (niter > 0) {
#pragma unroll
        for (int t = 0; t < 2; t++) {
            int r = pr + t * 32;
            uint32_t d = sb + (uint32_t)r * ARB + pj * 16;
            size_t gk = (size_t)r * DK + pj * 8;
            size_t gv = (size_t)r * SEQ + pj * 8;
            CP16(d, Khp + gk);
            CP16(d + 64 * ARB, Klp + gk);
            CP16(d + 128 * ARB, Vhp + gv);
            CP16(d + 192 * ARB, Vlp + gv);
        }
        CP_COMMIT();
    }

    // ---- stage Q (persistent region)
#pragma unroll
    for (int t = 0; t < 4; t++) {
        int i = tid + t * 256;
        int r = i >> 3, j = i & 7;
        char* dsth = smA + QOFF + (size_t)r * ARB + j * 16;
        char* dstl = smA + QOFF + (size_t)(128 + r) * ARB + j * 16;
        *(uint4*)dsth = *(const uint4*)(Qhp + (size_t)(q0 + r) * DK + j * 8);
        *(uint4*)dstl = *(const uint4*)(Qlp + (size_t)(q0 + r) * DK + j * 8);
    }
    CP_WAIT0();
    __syncthreads();  // Q visible + KV tile 0 visible

    const uint32_t aQb = sb + QOFF +
        (uint32_t)(wid * 16 + (lane & 15)) * ARB + (((lane >> 4) & 1) << 4);
    const uint32_t bro = (uint32_t)((lane & 7) + (((lane >> 4) & 1) << 3)) * ARB +
                         (((lane >> 3) & 1) << 4);

    float m0_ = -1e30f, m1_ = -1e30f, l0_ = 0.0f, l1_ = 0.0f;
    float o[8][4];
#pragma unroll
    for (int j = 0; j < 8; j++)
#pragma unroll
        for (int e = 0; e < 4; e++) o[j][e] = 0.0f;

    for (int it = 0; it < niter; it++) {
        const int cur = it & 1;
        const uint32_t stg = sb + (uint32_t)cur * ATILE;
        const int kt = it * 64;

        if (it + 1 < niter) {
            const int ktn = kt + 64;
            const uint32_t nstg = sb + (uint32_t)(1 - cur) * ATILE;
#pragma unroll
            for (int t = 0; t < 2; t++) {
                int r = pr + t * 32;
                uint32_t d = nstg + (uint32_t)r * ARB + pj * 16;
                size_t gk = (size_t)(ktn + r) * DK + pj * 8;
                size_t gv = (size_t)r * SEQ + ktn + pj * 8;
                CP16(d, Khp + gk);
                CP16(d + 64 * ARB, Klp + gk);
                CP16(d + 128 * ARB, Vhp + gv);
                CP16(d + 192 * ARB, Vlp + gv);
            }
            CP_COMMIT();
        }

        // ---- S = Q @ K^T (bf16x3, pass-reordered; S in log2 units)
        float s[8][4];
#pragma unroll
        for (int j = 0; j < 8; j++)
#pragma unroll
            for (int e = 0; e < 4; e++) s[j][e] = 0.0f;
        const uint32_t aKh = stg + bro, aKl = stg + 64 * ARB + bro;
#pragma unroll
        for (int ks = 0; ks < 4; ks++) {
            uint32_t qhf[4], qlf[4], kf[4][4];
            ldsm4(qhf, aQb + ks * 32);
            ldsm4(qlf, aQb + 128 * ARB + ks * 32);
#pragma unroll
            for (int nt2 = 0; nt2 < 4; nt2++)
                ldsm4(kf[nt2], aKh + nt2 * 16 * ARB + ks * 32);
#pragma unroll
            for (int nt2 = 0; nt2 < 4; nt2++)
#pragma unroll
                for (int q = 0; q < 2; q++)
                    mma16816(s[nt2 * 2 + q], qhf, &kf[nt2][q * 2]);
#pragma unroll
            for (int nt2 = 0; nt2 < 4; nt2++)
#pragma unroll
                for (int q = 0; q < 2; q++)
                    mma16816(s[nt2 * 2 + q], qlf, &kf[nt2][q * 2]);
#pragma unroll
            for (int nt2 = 0; nt2 < 4; nt2++)
                ldsm4(kf[nt2], aKl + nt2 * 16 * ARB + ks * 32);
#pragma unroll
            for (int nt2 = 0; nt2 < 4; nt2++)
#pragma unroll
                for (int q = 0; q < 2; q++)
                    mma16816(s[nt2 * 2 + q], qhf, &kf[nt2][q * 2]);
        }

        // ---- tail-tile masking (uniform branch; padded cols K=0 → s=0)
        if (kt + 64 > nk) {
#pragma unroll
            for (int nt = 0; nt < 8; nt++) {
                int cb = kt + nt * 8 + 2 * gc;
                if (cb >= nk)     { s[nt][0] = -3.0e38f; s[nt][2] = -3.0e38f; }
                if (cb + 1 >= nk) { s[nt][1] = -3.0e38f; s[nt][3] = -3.0e38f; }
            }
        }

        // ---- row max (log2 domain)
        float mx0 = -3.0e38f, mx1 = -3.0e38f;
#pragma unroll
        for (int nt = 0; nt < 8; nt++) {
            mx0 = fmaxf(mx0, fmaxf(s[nt][0], s[nt][1]));
            mx1 = fmaxf(mx1, fmaxf(s[nt][2], s[nt][3]));
        }
        mx0 = fmaxf(mx0, __shfl_xor_sync(0xffffffffu, mx0, 1));
        mx0 = fmaxf(mx0, __shfl_xor_sync(0xffffffffu, mx0, 2));
        mx1 = fmaxf(mx1, __shfl_xor_sync(0xffffffffu, mx1, 1));
        mx1 = fmaxf(mx1, __shfl_xor_sync(0xffffffffu, mx1, 2));
        float mn0 = fmaxf(m0_, mx0), mn1 = fmaxf(m1_, mx1);
        float al0 = fexp2m(m0_ - mn0), al1 = fexp2m(m1_ - mn1);
        m0_ = mn0;
        m1_ = mn1;

        // ---- exp + sums + pack P into mma A-fragments (hi/lo)
        uint32_t pa_h[4][4], pa_l[4][4];
        float sm0 = 0.0f, sm1 = 0.0f;
#pragma unroll
        for (int nt = 0; nt < 8; nt++) {
            float p0 = fexp2m(s[nt][0] - mn0);
            float p1 = fexp2m(s[nt][1] - mn0);
            float p2 = fexp2m(s[nt][2] - mn1);
            float p3 = fexp2m(s[nt][3] - mn1);
            sm0 += p0 + p1;
            sm1 += p2 + p3;
            int kp = nt >> 1, q = nt & 1;
            __nv_bfloat162 hb01 = __float22bfloat162_rn(make_float2(p0, p1));
            __nv_bfloat162 hb23 = __float22bfloat162_rn(make_float2(p2, p3));
            uint32_t u01 = *(uint32_t*)&hb01, u23 = *(uint32_t*)&hb23;
            pa_h[kp][q * 2 + 0] = u01;
            pa_h[kp][q * 2 + 1] = u23;
            float f0 = __int_as_float(u01 << 16);
            float f1 = __int_as_float(u01 & 0xFFFF0000u);
            float f2 = __int_as_float(u23 << 16);
            float f3 = __int_as_float(u23 & 0xFFFF0000u);
            __nv_bfloat162 lb01 = __float22bfloat162_rn(make_float2(p0 - f0, p1 - f1));
            __nv_bfloat162 lb23 = __float22bfloat162_rn(make_float2(p2 - f2, p3 - f3));
            pa_l[kp][q * 2 + 0] = *(uint32_t*)&lb01;
            pa_l[kp][q * 2 + 1] = *(uint32_t*)&lb23;
        }
        sm0 += __shfl_xor_sync(0xffffffffu, sm0, 1);
        sm0 += __shfl_xor_sync(0xffffffffu, sm0, 2);
        sm1 += __shfl_xor_sync(0xffffffffu, sm1, 1);
        sm1 += __shfl_xor_sync(0xffffffffu, sm1, 2);
        l0_ = l0_ * al0 + sm0;
        l1_ = l1_ * al1 + sm1;

#pragma unroll
        for (int j = 0; j < 8; j++) {
            o[j][0] *= al0;
            o[j][1] *= al0;
            o[j][2] *= al1;
            o[j][3] *= al1;
        }

        // ---- O += P @ V (bf16x3, pass-reordered)
        const uint32_t aVh = stg + 128 * ARB + bro, aVl = stg + 192 * ARB + bro;
#pragma unroll
        for (int kp = 0; kp < 4; kp++) {
            uint32_t vf[4][4];
#pragma unroll
            for (int nt2 = 0; nt2 < 4; nt2++)
                ldsm4(vf[nt2], aVh + nt2 * 16 * ARB + kp * 32);
#pragma unroll
            for (int nt2 = 0; nt2 < 4; nt2++)
#pragma unroll
                for (int q = 0; q < 2; q++)
                    mma16816(o[nt2 * 2 + q], pa_h[kp], &vf[nt2][q * 2]);
#pragma unroll
            for (int nt2 = 0; nt2 < 4; nt2++)
#pragma unroll
                for (int q = 0; q < 2; q++)
                    mma16816(o[nt2 * 2 + q], pa_l[kp], &vf[nt2][q * 2]);
#pragma unroll
            for (int nt2 = 0; nt2 < 4; nt2++)
                ldsm4(vf[nt2], aVl + nt2 * 16 * ARB + kp * 32);
#pragma unroll
            for (int nt2 = 0; nt2 < 4; nt2++)
#pragma unroll
                for (int q = 0; q < 2; q++)
                    mma16816(o[nt2 * 2 + q], pa_h[kp], &vf[nt2][q * 2]);
        }

        if (it + 1 < niter) {
            CP_WAIT0();
            __syncthreads();  // next tile visible; all reads of other stage done
        }
    }

    // ---- normalize + store bf16 hi/lo split at (B, L, H*64) for out-proj
    float inv0 = (l0_ > 0.0f) ? 1.0f / l0_ : 0.0f;
    float inv1 = (l1_ > 0.0f) ? 1.0f / l1_ : 0.0f;
    int r0 = q0 + wid * 16 + gr, r1 = r0 + 8;
    size_t base0 = (size_t)(b * SEQ + r0) * D_MODEL + h * DK;
    size_t base1 = (size_t)(b * SEQ + r1) * D_MODEL + h * DK;
#pragma unroll
    for (int nt = 0; nt < 8; nt++) {
        int cl = nt * 8 + 2 * gc;
        float v0 = o[nt][0] * inv0, v1 = o[nt][1] * inv0;
        float v2 = o[nt][2] * inv1, v3 = o[nt][3] * inv1;
        __nv_bfloat16 h0 = __float2bfloat16(v0), h1 = __float2bfloat16(v1);
        __nv_bfloat16 h2 = __float2bfloat16(v2), h3 = __float2bfloat16(v3);
        *(__nv_bfloat162*)(OutH + base0 + cl) = __halves2bfloat162(h0, h1);
        *(__nv_bfloat162*)(OutL + base0 + cl) = __halves2bfloat162(
            __float2bfloat16(v0 - __bfloat162float(h0)),
            __float2bfloat16(v1 - __bfloat162float(h1)));
        *(__nv_bfloat162*)(OutH + base1 + cl) = __halves2bfloat162(h2, h3);
        *(__nv_bfloat162*)(OutL + base1 + cl) = __halves2bfloat162(
            __float2bfloat16(v2 - __bfloat162float(h2)),
            __float2bfloat16(v3 - __bfloat162float(h3)));
    }
}

// ============================================================================
// Launch: 7 kernels total
// ============================================================================
extern "C" void kernel_launch(void* const* d_in, const int* in_sizes, int n_in,
                              void* d_out, int out_size) {
    const float* query = (const float*)d_in[0];
    const float* key   = (const float*)d_in[1];
    const float* value = (const float*)d_in[2];
    const int*   mask  = (const int*)d_in[3];
    const float* Wq = (const float*)d_in[4];
    const float* bq = (const float*)d_in[5];
    const float* Wk = (const float*)d_in[6];
    const float* bk = (const float*)d_in[7];
    const float* Wv = (const float*)d_in[8];
    const float* bv = (const float*)d_in[9];
    const float* Wo = (const float*)d_in[10];
    const float* bo = (const float*)d_in[11];

    __nv_bfloat16 *Ah, *Al, *Wth, *Wtl, *Qh, *Ql, *Kh, *Kl, *Khc, *Klc, *Vth, *Vtl;
    float *Vf;
    int *idx, *nk;
    cudaGetSymbolAddress((void**)&Ah, g_Ah);
    cudaGetSymbolAddress((void**)&Al, g_Al);
    cudaGetSymbolAddress((void**)&Wth, g_Wth);
    cudaGetSymbolAddress((void**)&Wtl, g_Wtl);
    cudaGetSymbolAddress((void**)&Qh, g_Qh);
    cudaGetSymbolAddress((void**)&Ql, g_Ql);
    cudaGetSymbolAddress((void**)&Kh, g_Kh);
    cudaGetSymbolAddress((void**)&Kl, g_Kl);
    cudaGetSymbolAddress((void**)&Khc, g_Khc);
    cudaGetSymbolAddress((void**)&Klc, g_Klc);
    cudaGetSymbolAddress((void**)&Vf, g_Vf);
    cudaGetSymbolAddress((void**)&Vth, g_Vth);
    cudaGetSymbolAddress((void**)&Vtl, g_Vtl);
    cudaGetSymbolAddress((void**)&idx, g_idx);
    cudaGetSymbolAddress((void**)&nk, g_nk);

    cudaFuncSetAttribute(mm_gemm, cudaFuncAttributeMaxDynamicSharedMemorySize,
                         G_SMEM);
    cudaFuncSetAttribute(mm_attn, cudaFuncAttributeMaxDynamicSharedMemorySize,
                         A_SMEM);

    const int N4 = MT * D_MODEL / 4;

    mask_scan_kernel<<<BATCH, 1024>>>(mask, idx, nk);
    wt_split_b_kernel<<<dim3(16, 16, 4), dim3(32, 32)>>>(Wq, Wk, Wv, Wo, Wth, Wtl);
    split_b_kernel<<<dim3(N4 / 256, 3), 256>>>((const float4*)query,
                                               (const float4*)key,
                                               (const float4*)value, Ah, Al, N4);
    mm_gemm<<<dim3(4, 64, 3), 256, G_SMEM>>>(Ah, Al, Wth, Wtl, bq, bk, bv, bo,
                                             Qh, Ql, Kh, Kl, Vf, nullptr, 0);
    kv_gather_kernel<<<dim3(SEQ / 64, BH), 256>>>(Kh, Kl, Vf, idx, nk,
                                                  Khc, Klc, Vth, Vtl);
    mm_attn<<<dim3(SEQ / 128, BH), 256, A_SMEM>>>(Qh, Ql, Khc, Klc, Vth, Vtl,
                                                  nk, Ah, Al);
    mm_gemm<<<dim3(4, 64, 1), 256, G_SMEM>>>(Ah, Al, Wth, Wtl, bq, bk, bv, bo,
                                             nullptr, nullptr, nullptr, nullptr,
                                             nullptr, (float*)d_out, 3);
}